// round 8
// baseline (speedup 1.0000x reference)
#include <cuda_runtime.h>
#include <math.h>

// ---------------- problem constants ----------------
#define BB 4
#define SS 512
#define DD 768
#define FF_ 3072
#define VV 30000
#define HH 12
#define MM 64
#define DH 64
#define NLAYERS 12

// ---------------- static device scratch ----------------
__device__ float g_x [BB*SS*DD];
__device__ float g_y [BB*SS*DD];
__device__ float g_q [BB*SS*DD];
__device__ float g_k [BB*SS*DD];
__device__ float g_v [BB*SS*DD];
__device__ float g_att[BB*HH*SS*SS];
__device__ float g_h1[BB*SS*FF_];
__device__ float g_g [BB*MM*DD];
__device__ int   g_tok[BB*SS];

// ---------------- epilogue flags ----------------
#define EPI_BIAS  1
#define EPI_RELU  2
#define EPI_RESID 4

// ======================================================================
// Tiled fp32 GEMM: C[z] = scale * A[z] @ op(B[z]) (+bias)(+relu)(+resid)
// BM=128, BN=64, BK=16, 256 threads, 8x4 micro-tile per thread.
// Batched via blockIdx.z decomposed as (zb, zh) with independent strides.
// Assumes: M % 128 == 0, K % 16 == 0, lda/ldb/ldc and base offsets % 4 == 0.
// N may be ragged (guarded).  TRANS_B path assumes N % 64 == 0 (true here).
// ======================================================================
template<int EPI, bool TB>
__global__ void __launch_bounds__(256)
gemm_k(const float* __restrict__ A, const float* __restrict__ B,
       float* __restrict__ C, const float* __restrict__ bias,
       const float* __restrict__ resid,
       int M, int N, int K, int lda, int ldb, int ldc, float scale,
       int batchH, long long sAb, long long sAh, long long sBb, long long sBh,
       long long sCb, long long sCh)
{
    constexpr int BM = 128, BN = 64, BK = 16;
    __shared__ float As[BK][BM];
    __shared__ float Bs[BK][BN];

    int z  = blockIdx.z;
    int zb = z / batchH;
    int zh = z - zb * batchH;
    A += zb * sAb + zh * sAh;
    B += zb * sBb + zh * sBh;
    long long coff = zb * sCb + zh * sCh;
    C += coff;
    if (EPI & EPI_RESID) resid += coff;

    const int m0  = blockIdx.y * BM;
    const int n0  = blockIdx.x * BN;
    const int tid = threadIdx.x;
    const int tx  = tid & 15;
    const int ty  = tid >> 4;

    // A-tile load mapping: 256 threads, each loads 8 consecutive k (2 x float4)
    const int ar = tid >> 1;          // 0..127 (row within tile)
    const int ak = (tid & 1) * 8;     // 0 or 8

    // B-tile load mapping
    int bk, bn;
    if (TB) { bn = tid >> 2; bk = (tid & 3) * 4; }   // B is [N,K]
    else    { bk = tid >> 4; bn = (tid & 15) * 4; }  // B is [K,N]

    float acc[8][4];
#pragma unroll
    for (int i = 0; i < 8; i++)
#pragma unroll
        for (int j = 0; j < 4; j++) acc[i][j] = 0.f;

    for (int k0 = 0; k0 < K; k0 += BK) {
        // ---- load A tile (always in range: M%128==0, K%16==0) ----
        {
            const float* Ap = A + (size_t)(m0 + ar) * lda + (k0 + ak);
            float4 a0 = *(const float4*)Ap;
            float4 a1 = *(const float4*)(Ap + 4);
            As[ak + 0][ar] = a0.x; As[ak + 1][ar] = a0.y;
            As[ak + 2][ar] = a0.z; As[ak + 3][ar] = a0.w;
            As[ak + 4][ar] = a1.x; As[ak + 5][ar] = a1.y;
            As[ak + 6][ar] = a1.z; As[ak + 7][ar] = a1.w;
        }
        // ---- load B tile ----
        if (TB) {
            const float* Bp = B + (size_t)(n0 + bn) * ldb + (k0 + bk);
            float4 b4 = *(const float4*)Bp;
            Bs[bk + 0][bn] = b4.x; Bs[bk + 1][bn] = b4.y;
            Bs[bk + 2][bn] = b4.z; Bs[bk + 3][bn] = b4.w;
        } else {
            int n = n0 + bn;
            float4 b4;
            if (n + 3 < N) {
                b4 = *(const float4*)(B + (size_t)(k0 + bk) * ldb + n);
            } else {
                float t0 = (n + 0 < N) ? B[(size_t)(k0 + bk) * ldb + n + 0] : 0.f;
                float t1 = (n + 1 < N) ? B[(size_t)(k0 + bk) * ldb + n + 1] : 0.f;
                float t2 = (n + 2 < N) ? B[(size_t)(k0 + bk) * ldb + n + 2] : 0.f;
                float t3 = (n + 3 < N) ? B[(size_t)(k0 + bk) * ldb + n + 3] : 0.f;
                b4 = make_float4(t0, t1, t2, t3);
            }
            *(float4*)&Bs[bk][bn] = b4;
        }
        __syncthreads();

#pragma unroll
        for (int kk = 0; kk < BK; kk++) {
            float4 a0 = *(const float4*)&As[kk][ty * 8];
            float4 a1 = *(const float4*)&As[kk][ty * 8 + 4];
            float4 bv = *(const float4*)&Bs[kk][tx * 4];
            float a[8] = {a0.x, a0.y, a0.z, a0.w, a1.x, a1.y, a1.z, a1.w};
            float b[4] = {bv.x, bv.y, bv.z, bv.w};
#pragma unroll
            for (int i = 0; i < 8; i++)
#pragma unroll
                for (int j = 0; j < 4; j++)
                    acc[i][j] = fmaf(a[i], b[j], acc[i][j]);
        }
        __syncthreads();
    }

    // ---- epilogue ----
    const int cm = m0 + ty * 8;
    const int cn = n0 + tx * 4;
    float bvv[4] = {0.f, 0.f, 0.f, 0.f};
    if (EPI & EPI_BIAS) {
#pragma unroll
        for (int j = 0; j < 4; j++)
            if (cn + j < N) bvv[j] = bias[cn + j];
    }
#pragma unroll
    for (int i = 0; i < 8; i++) {
        int r = cm + i;
#pragma unroll
        for (int j = 0; j < 4; j++) {
            int c = cn + j;
            if (c < N) {
                float v = acc[i][j] * scale;
                if (EPI & EPI_BIAS)  v += bvv[j];
                if (EPI & EPI_RELU)  v = fmaxf(v, 0.f);
                if (EPI & EPI_RESID) v += resid[(size_t)r * ldc + c];
                C[(size_t)r * ldc + c] = v;
            }
        }
    }
}

// ======================================================================
// one-hot -> token id (each row has exactly one 1.0)
// ======================================================================
__global__ void findtok_k(const float* __restrict__ oh, int* __restrict__ tok)
{
    size_t row = blockIdx.x;
    const float* r = oh + row * (size_t)VV;
    for (int j = threadIdx.x; j < VV; j += blockDim.x)
        if (r[j] > 0.5f) tok[row] = j;
}

// ======================================================================
// x = se_w[tok] + se_b + positional encoding
// pe[s,d]: raw = s / 10000^(2d/D); s==0 -> 0; else sin(raw) for even d,
// cos(raw) for odd d (matches reference exactly incl. per-column exponent).
// ======================================================================
__global__ void embed_k(const float* __restrict__ se_w, const float* __restrict__ se_b,
                        const int* __restrict__ tok, float* __restrict__ x)
{
    int row = blockIdx.x;           // b*S + s
    int s   = row & (SS - 1);
    int tk  = tok[row];
    const float* wrow = se_w + (size_t)tk * DD;
    float* xr = x + (size_t)row * DD;
    for (int d = threadIdx.x; d < DD; d += blockDim.x) {
        float pe = 0.f;
        if (s != 0) {
            float denom = powf(10000.0f, (2.0f * (float)d) / (float)DD);
            float raw   = (float)s / denom;
            pe = (d & 1) ? cosf(raw) : sinf(raw);
        }
        xr[d] = wrow[d] + se_b[d] + pe;
    }
}

// ======================================================================
// row softmax over 512 (one block per row, 256 threads, float2 per thread)
// ======================================================================
__global__ void softmax_k(float* __restrict__ att)
{
    __shared__ float red[8];
    size_t row = blockIdx.x;
    float2* p = reinterpret_cast<float2*>(att) + row * 256;
    int t = threadIdx.x;
    float2 v = p[t];
    float m = fmaxf(v.x, v.y);
#pragma unroll
    for (int o = 16; o; o >>= 1) m = fmaxf(m, __shfl_xor_sync(0xffffffffu, m, o));
    if ((t & 31) == 0) red[t >> 5] = m;
    __syncthreads();
    m = fmaxf(fmaxf(fmaxf(red[0], red[1]), fmaxf(red[2], red[3])),
              fmaxf(fmaxf(red[4], red[5]), fmaxf(red[6], red[7])));
    float ex = expf(v.x - m), ey = expf(v.y - m);
    float s = ex + ey;
#pragma unroll
    for (int o = 16; o; o >>= 1) s += __shfl_xor_sync(0xffffffffu, s, o);
    __syncthreads();
    if ((t & 31) == 0) red[t >> 5] = s;
    __syncthreads();
    s = red[0] + red[1] + red[2] + red[3] + red[4] + red[5] + red[6] + red[7];
    float inv = 1.0f / s;
    p[t] = make_float2(ex * inv, ey * inv);
}

// ======================================================================
// layernorm over D=768 (block per row, 256 threads, 3 elems each)
// ======================================================================
__global__ void layernorm_k(const float* __restrict__ y, float* __restrict__ x)
{
    __shared__ float rs[8], rq[8];
    size_t row = blockIdx.x;
    const float* yp = y + row * DD;
    float* xp = x + row * DD;
    int t = threadIdx.x;
    float a0 = yp[t], a1 = yp[t + 256], a2 = yp[t + 512];
    float s = a0 + a1 + a2;
    float q = a0 * a0 + a1 * a1 + a2 * a2;
#pragma unroll
    for (int o = 16; o; o >>= 1) {
        s += __shfl_xor_sync(0xffffffffu, s, o);
        q += __shfl_xor_sync(0xffffffffu, q, o);
    }
    if ((t & 31) == 0) { rs[t >> 5] = s; rq[t >> 5] = q; }
    __syncthreads();
    s = rs[0] + rs[1] + rs[2] + rs[3] + rs[4] + rs[5] + rs[6] + rs[7];
    q = rq[0] + rq[1] + rq[2] + rq[3] + rq[4] + rq[5] + rq[6] + rq[7];
    float mean = s * (1.0f / (float)DD);
    float var  = q * (1.0f / (float)DD) - mean * mean;
    float r = rsqrtf(var + 1e-5f);
    xp[t]       = (a0 - mean) * r;
    xp[t + 256] = (a1 - mean) * r;
    xp[t + 512] = (a2 - mean) * r;
}

// ======================================================================
// gather masked rows: g[b*M+m, :] = x[b*S + idx[b,m], :]
// ======================================================================
__global__ void gather_k(const float* __restrict__ x, const int* __restrict__ idx,
                         float* __restrict__ g)
{
    int r = blockIdx.x;         // 0..B*M-1
    int b = r >> 6;             // M == 64
    int s = idx[r];
    const float* src = x + ((size_t)(b * SS + s)) * DD;
    float* dst = g + (size_t)r * DD;
    for (int d = threadIdx.x; d < DD; d += blockDim.x) dst[d] = src[d];
}

// ======================================================================
// in-place log_softmax over V=30000 (block per row)
// ======================================================================
__global__ void logsoftmax_k(float* __restrict__ out)
{
    __shared__ float red[8];
    size_t row = blockIdx.x;
    float* p = out + row * (size_t)VV;
    int t = threadIdx.x;

    float m = -1e30f;
    for (int j = t; j < VV; j += 256) m = fmaxf(m, p[j]);
#pragma unroll
    for (int o = 16; o; o >>= 1) m = fmaxf(m, __shfl_xor_sync(0xffffffffu, m, o));
    if ((t & 31) == 0) red[t >> 5] = m;
    __syncthreads();
    m = fmaxf(fmaxf(fmaxf(red[0], red[1]), fmaxf(red[2], red[3])),
              fmaxf(fmaxf(red[4], red[5]), fmaxf(red[6], red[7])));

    float s = 0.f;
    for (int j = t; j < VV; j += 256) s += expf(p[j] - m);
#pragma unroll
    for (int o = 16; o; o >>= 1) s += __shfl_xor_sync(0xffffffffu, s, o);
    __syncthreads();
    if ((t & 31) == 0) red[t >> 5] = s;
    __syncthreads();
    s = red[0] + red[1] + red[2] + red[3] + red[4] + red[5] + red[6] + red[7];

    float lse = m + logf(s);
    for (int j = t; j < VV; j += 256) p[j] = p[j] - lse;
}

// ======================================================================
// launcher
// ======================================================================
extern "C" void kernel_launch(void* const* d_in, const int* in_sizes, int n_in,
                              void* d_out, int out_size)
{
    (void)in_sizes; (void)n_in; (void)out_size;
    const float* onehot = (const float*)d_in[0];
    const float* se_w = (const float*)d_in[1];
    const float* se_b = (const float*)d_in[2];
    const float* wq = (const float*)d_in[3];  const float* bq = (const float*)d_in[4];
    const float* wk = (const float*)d_in[5];  const float* bk = (const float*)d_in[6];
    const float* wv = (const float*)d_in[7];  const float* bv = (const float*)d_in[8];
    const float* wo = (const float*)d_in[9];  const float* bo = (const float*)d_in[10];
    const float* w1 = (const float*)d_in[11]; const float* b1 = (const float*)d_in[12];
    const float* w2 = (const float*)d_in[13]; const float* b2 = (const float*)d_in[14];
    const float* we = (const float*)d_in[15]; const float* be = (const float*)d_in[16];
    const int*   idx = (const int*)d_in[17];
    float* out = (float*)d_out;

    // resolve device-global scratch addresses (pure lookups, capture-safe)
    float *px, *py, *pq, *pk, *pv, *patt, *ph1, *pg; int* ptok;
    cudaGetSymbolAddress((void**)&px,   g_x);
    cudaGetSymbolAddress((void**)&py,   g_y);
    cudaGetSymbolAddress((void**)&pq,   g_q);
    cudaGetSymbolAddress((void**)&pk,   g_k);
    cudaGetSymbolAddress((void**)&pv,   g_v);
    cudaGetSymbolAddress((void**)&patt, g_att);
    cudaGetSymbolAddress((void**)&ph1,  g_h1);
    cudaGetSymbolAddress((void**)&pg,   g_g);
    cudaGetSymbolAddress((void**)&ptok, g_tok);

    const int Mrows = BB * SS;       // 2048
    const float scl = 0.125f;        // 1/sqrt(64)

    // ---- embedding ----
    findtok_k<<<Mrows, 256>>>(onehot, ptok);
    embed_k<<<Mrows, 256>>>(se_w, se_b, ptok, px);

    const long long sQKb = (long long)SS * DD;   // per-batch stride in q/k/v/o
    const long long sQKh = DH;                   // per-head stride
    const long long sAb  = (long long)HH * SS * SS;
    const long long sAh  = (long long)SS * SS;

    for (int l = 0; l < NLAYERS; l++) {
        // QKV projections: [2048,768] @ [768,768] + bias
        dim3 gp((DD + 63) / 64, Mrows / 128, 1);
        gemm_k<EPI_BIAS, false><<<gp, 256>>>(px, wq, pq, bq, nullptr,
            Mrows, DD, DD, DD, DD, DD, 1.f, 1, 0, 0, 0, 0, 0, 0);
        gemm_k<EPI_BIAS, false><<<gp, 256>>>(px, wk, pk, bk, nullptr,
            Mrows, DD, DD, DD, DD, DD, 1.f, 1, 0, 0, 0, 0, 0, 0);
        gemm_k<EPI_BIAS, false><<<gp, 256>>>(px, wv, pv, bv, nullptr,
            Mrows, DD, DD, DD, DD, DD, 1.f, 1, 0, 0, 0, 0, 0, 0);

        // scores: att[b,h] = scale * q[b,:,h,:] @ k[b,:,h,:]^T   (48 batches)
        dim3 gs(SS / 64, SS / 128, BB * HH);
        gemm_k<0, true><<<gs, 256>>>(pq, pk, patt, nullptr, nullptr,
            SS, SS, DH, DD, DD, SS, scl, HH, sQKb, sQKh, sQKb, sQKh, sAb, sAh);

        // softmax over last dim
        softmax_k<<<BB * HH * SS, 256>>>(patt);

        // o[b,:,h,:] = att[b,h] @ v[b,:,h,:]  (write into pq, q is dead)
        dim3 ga(1, SS / 128, BB * HH);
        gemm_k<0, false><<<ga, 256>>>(patt, pv, pq, nullptr, nullptr,
            SS, DH, SS, SS, DD, DD, 1.f, HH, sAb, sAh, sQKb, sQKh, sQKb, sQKh);

        // y = o @ wo + bo + x   (residual)
        gemm_k<EPI_BIAS | EPI_RESID, false><<<gp, 256>>>(pq, wo, py, bo, px,
            Mrows, DD, DD, DD, DD, DD, 1.f, 1, 0, 0, 0, 0, 0, 0);

        // x = layernorm(y)
        layernorm_k<<<Mrows, 256>>>(py, px);

        // h1 = relu(x @ w1 + b1)
        dim3 gf1((FF_ + 63) / 64, Mrows / 128, 1);
        gemm_k<EPI_BIAS | EPI_RELU, false><<<gf1, 256>>>(px, w1, ph1, b1, nullptr,
            Mrows, FF_, DD, DD, FF_, FF_, 1.f, 1, 0, 0, 0, 0, 0, 0);

        // x = h1 @ w2 + b2   (no residual, matches reference)
        gemm_k<EPI_BIAS, false><<<gp, 256>>>(ph1, w2, px, b2, nullptr,
            Mrows, DD, FF_, FF_, DD, DD, 1.f, 1, 0, 0, 0, 0, 0, 0);
    }

    // gather masked rows, project to vocab, log_softmax
    gather_k<<<BB * MM, 256>>>(px, idx, pg);
    dim3 ge((VV + 63) / 64, (BB * MM) / 128, 1);
    gemm_k<EPI_BIAS, false><<<ge, 256>>>(pg, we, out, be, nullptr,
        BB * MM, VV, DD, DD, VV, VV, 1.f, 1, 0, 0, 0, 0, 0, 0);
    logsoftmax_k<<<BB * MM, 256>>>(out);
}

// round 10
// speedup vs baseline: 5.0752x; 5.0752x over previous
#include <cuda_runtime.h>
#include <cuda_bf16.h>
#include <math.h>

// ---------------- problem constants ----------------
#define BB 4
#define SS 512
#define DD 768
#define FF_ 3072
#define VV 30000
#define VPAD 30080
#define HH 12
#define MM 64
#define DH 64
#define NLAYERS 12

// ---------------- static device scratch ----------------
__device__ float g_x  [BB*SS*DD];
__device__ float g_y  [BB*SS*DD];
__device__ float g_att[BB*HH*SS*SS];
__device__ float g_bqkv[3*DD];
__device__ __nv_bfloat16 g_xb  [BB*SS*DD];
__device__ __nv_bfloat16 g_lnb [BB*SS*DD];
__device__ __nv_bfloat16 g_ob  [BB*SS*DD];
__device__ __nv_bfloat16 g_qb  [BB*HH*SS*DH];
__device__ __nv_bfloat16 g_kb  [BB*HH*SS*DH];
__device__ __nv_bfloat16 g_vtb [BB*HH*DH*SS];
__device__ __nv_bfloat16 g_attb[BB*HH*SS*SS];
__device__ __nv_bfloat16 g_h1b [BB*SS*FF_];
__device__ __nv_bfloat16 g_gb  [BB*MM*DD];
__device__ __nv_bfloat16 g_wqkv[3*DD*DD];   // [n=2304][k=768]
__device__ __nv_bfloat16 g_wow [DD*DD];     // [n][k]
__device__ __nv_bfloat16 g_w1w [FF_*DD];    // [3072][768]
__device__ __nv_bfloat16 g_w2w [DD*FF_];    // [768][3072]
__device__ __nv_bfloat16 g_wew [VPAD*DD];   // [30080][768], rows >= 30000 zero
__device__ int g_tok[BB*SS];

// ====================== PTX helpers (arch-portable) ====================
__device__ __forceinline__ unsigned smem_u32(const void* p) {
    unsigned a;
    asm("{ .reg .u64 t; cvta.to.shared.u64 t, %1; cvt.u32.u64 %0, t; }" : "=r"(a) : "l"(p));
    return a;
}
#define SWZ(off) ((unsigned)(off) ^ (((unsigned)(off) >> 3) & 0x70u))

#define CP_ASYNC16(dst, src) \
    asm volatile("cp.async.cg.shared.global [%0], [%1], 16;" :: "r"(dst), "l"(src))
#define CP_COMMIT() asm volatile("cp.async.commit_group;" ::: "memory")
#define CP_WAIT1()  asm volatile("cp.async.wait_group 1;" ::: "memory")
#define CP_WAIT0()  asm volatile("cp.async.wait_group 0;" ::: "memory")

#define LDSM4(r, addr) \
    asm volatile("ldmatrix.sync.aligned.m8n8.x4.shared.b16 {%0,%1,%2,%3}, [%4];" \
        : "=r"((r)[0]), "=r"((r)[1]), "=r"((r)[2]), "=r"((r)[3]) : "r"(addr))

#define MMA16816(c, a, b0, b1) \
    asm volatile("mma.sync.aligned.m16n8k16.row.col.f32.bf16.bf16.f32 " \
        "{%0,%1,%2,%3}, {%4,%5,%6,%7}, {%8,%9}, {%0,%1,%2,%3};" \
        : "+f"((c)[0]), "+f"((c)[1]), "+f"((c)[2]), "+f"((c)[3]) \
        : "r"((a)[0]), "r"((a)[1]), "r"((a)[2]), "r"((a)[3]), "r"(b0), "r"(b1))

// ---------------- epilogue modes ----------------
#define EP_QKV   0
#define EP_SCORE 1
#define EP_ATTV  2
#define EP_OPROJ 3
#define EP_FFN1  4
#define EP_FFN2  5
#define EP_HEAD  6

template<int EPI>
__device__ __forceinline__ void epi_store(int r, int c, float v, int z,
                                          const float* __restrict__ bias,
                                          float* __restrict__ outp)
{
    if (EPI == EP_QKV) {
        int b = r >> 9, s = r & 511;
        float val = v + bias[c];
        int which = c / DD, rr = c - which * DD, h = rr >> 6, d = rr & 63;
        __nv_bfloat16 bv = __float2bfloat16(val);
        if (which == 2)
            g_vtb[((size_t)(b * HH + h) * DH + d) * SS + s] = bv;
        else {
            size_t base = ((size_t)(b * HH + h) * SS + s) * DH + d;
            if (which == 0) g_qb[base] = bv; else g_kb[base] = bv;
        }
    } else if (EPI == EP_SCORE) {
        g_att[(size_t)z * SS * SS + (size_t)r * SS + c] = v * 0.125f;
    } else if (EPI == EP_ATTV) {
        int b = z / HH, h = z - b * HH;
        g_ob[((size_t)(b * SS + r)) * DD + h * DH + c] = __float2bfloat16(v);
    } else if (EPI == EP_OPROJ) {
        size_t off = (size_t)r * DD + c;
        g_y[off] = v + bias[c] + g_x[off];
    } else if (EPI == EP_FFN1) {
        g_h1b[(size_t)r * FF_ + c] = __float2bfloat16(fmaxf(v + bias[c], 0.f));
    } else if (EPI == EP_FFN2) {
        size_t off = (size_t)r * DD + c;
        float val = v + bias[c];
        g_x[off]  = val;
        g_xb[off] = __float2bfloat16(val);
    } else { // EP_HEAD
        if (c < VV) outp[(size_t)r * VV + c] = v + bias[c];
    }
}

// ======================================================================
// bf16 mma.sync GEMM:  D[128 x NT] = A_tile @ B_tile^T  (fp32 accum)
// A: [M,K] bf16 K-major (lda).  B: [N,K] bf16 K-major (ldb).
// Grid: (N/NT, M/128, Z).  K multiple of 64.  BK=64, cp.async double buffer,
// SW128-swizzled smem, ldmatrix.x4 fragments, fused per-mode epilogue.
// ======================================================================
template<int EPI, int NT>
__global__ void __launch_bounds__(256)
tgemm_k(const __nv_bfloat16* __restrict__ A, const __nv_bfloat16* __restrict__ B,
        int K, int lda, int ldb, long long sAz, long long sBz,
        const float* __restrict__ bias, float* __restrict__ outp)
{
    extern __shared__ char dsm[];
    constexpr int ABUF = 128 * 128;     // 16 KB: 128 rows x 128 B
    constexpr int BBUF = NT * 128;      // NT rows x 128 B
    constexpr int WN   = NT / 2;        // warp n-extent (2 warps along N)
    constexpr int NTW  = WN / 8;        // n-tiles (8 wide) per warp

    const int tid  = threadIdx.x;
    const int lane = tid & 31, wid = tid >> 5;
    const int wm = wid & 3, wn = wid >> 2;            // 4 x 2 warp grid
    const int m0 = blockIdx.y * 128, n0 = blockIdx.x * NT;
    const int z  = blockIdx.z;
    const unsigned sb = smem_u32(dsm);

    A += (size_t)z * sAz + (size_t)m0 * lda;
    B += (size_t)z * sBz + (size_t)n0 * ldb;

    const int NC = K >> 6;

    float acc[2][NTW][4];
#pragma unroll
    for (int i = 0; i < 2; i++)
#pragma unroll
        for (int j = 0; j < NTW; j++)
#pragma unroll
            for (int k = 0; k < 4; k++) acc[i][j][k] = 0.f;

    // ---- chunk loader: 64-k slab of A (128 rows) and B (NT rows) ----
    auto load_chunk = [&](int kc, int buf) {
        const __nv_bfloat16* Ap = A + kc * 64;
        unsigned ab = sb + buf * ABUF;
#pragma unroll
        for (int i = 0; i < 4; i++) {                 // 1024 16B chunks
            int ch = tid + i * 256;
            int row = ch >> 3, c = ch & 7;
            CP_ASYNC16(ab + SWZ(row * 128 + c * 16), Ap + (size_t)row * lda + c * 8);
        }
        const __nv_bfloat16* Bp = B + kc * 64;
        unsigned bb = sb + 2 * ABUF + buf * BBUF;
#pragma unroll
        for (int i = 0; i < NT / 32; i++) {           // NT*8 chunks
            int ch = tid + i * 256;
            int row = ch >> 3, c = ch & 7;
            CP_ASYNC16(bb + SWZ(row * 128 + c * 16), Bp + (size_t)row * ldb + c * 8);
        }
        CP_COMMIT();
    };

    load_chunk(0, 0);

    // fragment address components (constant across k-loop)
    const int a_row_lo = (lane & 15);                 // row within 16-row tile
    const int a_half   = (lane >> 4);                 // 0/1 -> k cols 0-7 / 8-15
    const int b_noff   = (lane & 7) + ((lane >> 4) << 3);
    const int b_half   = (lane >> 3) & 1;

    for (int kc = 0; kc < NC; kc++) {
        const int buf = kc & 1;
        if (kc + 1 < NC) { load_chunk(kc + 1, buf ^ 1); CP_WAIT1(); }
        else             { CP_WAIT0(); }
        __syncthreads();

        const unsigned ab = sb + buf * ABUF;
        const unsigned bb = sb + 2 * ABUF + buf * BBUF;
#pragma unroll
        for (int ks = 0; ks < 4; ks++) {              // 4 x k16 steps
            unsigned a[2][4];
#pragma unroll
            for (int mt = 0; mt < 2; mt++) {
                int row = wm * 32 + mt * 16 + a_row_lo;
                LDSM4(a[mt], ab + SWZ(row * 128 + ks * 32 + a_half * 16));
            }
#pragma unroll
            for (int ntp = 0; ntp < NTW / 2; ntp++) {
                unsigned b[4];
                int nrow = wn * WN + ntp * 16 + b_noff;
                LDSM4(b, bb + SWZ(nrow * 128 + ks * 32 + b_half * 16));
#pragma unroll
                for (int mt = 0; mt < 2; mt++) {
                    MMA16816(acc[mt][2 * ntp],     a[mt], b[0], b[1]);
                    MMA16816(acc[mt][2 * ntp + 1], a[mt], b[2], b[3]);
                }
            }
        }
        __syncthreads();
    }

    // ---- epilogue ----
    const int g = lane >> 2, t = lane & 3;
#pragma unroll
    for (int mt = 0; mt < 2; mt++) {
#pragma unroll
        for (int nt = 0; nt < NTW; nt++) {
            int r0 = m0 + wm * 32 + mt * 16 + g;
            int c0 = n0 + wn * WN + nt * 8 + t * 2;
            epi_store<EPI>(r0,     c0,     acc[mt][nt][0], z, bias, outp);
            epi_store<EPI>(r0,     c0 + 1, acc[mt][nt][1], z, bias, outp);
            epi_store<EPI>(r0 + 8, c0,     acc[mt][nt][2], z, bias, outp);
            epi_store<EPI>(r0 + 8, c0 + 1, acc[mt][nt][3], z, bias, outp);
        }
    }
}

// ======================================================================
// weight transpose+pack: src fp32 [K,N] row-major -> dst bf16 [Npad,K];
// rows n in [N,Npad) zero-filled.
// ======================================================================
__global__ void packT_k(const float* __restrict__ src, __nv_bfloat16* __restrict__ dst,
                        int K, int N, int Npad)
{
    __shared__ float t[32][33];
    int n0 = blockIdx.x * 32, k0 = blockIdx.y * 32;
    int tx = threadIdx.x, ty = threadIdx.y;    // 32 x 8
#pragma unroll
    for (int i = 0; i < 4; i++) {
        int k = k0 + ty + i * 8, n = n0 + tx;
        t[ty + i * 8][tx] = (k < K && n < N) ? src[(size_t)k * N + n] : 0.f;
    }
    __syncthreads();
#pragma unroll
    for (int i = 0; i < 4; i++) {
        int n = n0 + ty + i * 8, k = k0 + tx;
        if (n < Npad && k < K) dst[(size_t)n * K + k] = __float2bfloat16(t[tx][ty + i * 8]);
    }
}

__global__ void packb_k(const float* __restrict__ bq, const float* __restrict__ bk,
                        const float* __restrict__ bv, float* __restrict__ dst)
{
    int i = blockIdx.x * 256 + threadIdx.x;
    if (i < DD) dst[i] = bq[i];
    else if (i < 2 * DD) dst[i] = bk[i - DD];
    else if (i < 3 * DD) dst[i] = bv[i - 2 * DD];
}

// ======================================================================
// one-hot -> token id
// ======================================================================
__global__ void findtok_k(const float* __restrict__ oh, int* __restrict__ tok)
{
    size_t row = blockIdx.x;
    const float* r = oh + row * (size_t)VV;
    for (int j = threadIdx.x; j < VV; j += blockDim.x)
        if (r[j] > 0.5f) tok[row] = j;
}

// ======================================================================
// x = se_w[tok] + se_b + positional encoding ; also bf16 mirror
// ======================================================================
__global__ void embed_k(const float* __restrict__ se_w, const float* __restrict__ se_b,
                        const int* __restrict__ tok, float* __restrict__ x,
                        __nv_bfloat16* __restrict__ xb)
{
    int row = blockIdx.x;
    int s   = row & (SS - 1);
    int tk  = tok[row];
    const float* wrow = se_w + (size_t)tk * DD;
    float* xr = x + (size_t)row * DD;
    __nv_bfloat16* xbr = xb + (size_t)row * DD;
    for (int d = threadIdx.x; d < DD; d += blockDim.x) {
        float pe = 0.f;
        if (s != 0) {
            float denom = powf(10000.0f, (2.0f * (float)d) / (float)DD);
            float raw   = (float)s / denom;
            pe = (d & 1) ? cosf(raw) : sinf(raw);
        }
        float v = wrow[d] + se_b[d] + pe;
        xr[d] = v;
        xbr[d] = __float2bfloat16(v);
    }
}

// ======================================================================
// row softmax over 512 (fp32 in -> bf16 out)
// ======================================================================
__global__ void softmax_k(const float* __restrict__ att, __nv_bfloat16* __restrict__ attb)
{
    __shared__ float red[8];
    size_t row = blockIdx.x;
    const float2* p = reinterpret_cast<const float2*>(att) + row * 256;
    __nv_bfloat162* q = reinterpret_cast<__nv_bfloat162*>(attb) + row * 256;
    int t = threadIdx.x;
    float2 v = p[t];
    float m = fmaxf(v.x, v.y);
#pragma unroll
    for (int o = 16; o; o >>= 1) m = fmaxf(m, __shfl_xor_sync(0xffffffffu, m, o));
    if ((t & 31) == 0) red[t >> 5] = m;
    __syncthreads();
    m = fmaxf(fmaxf(fmaxf(red[0], red[1]), fmaxf(red[2], red[3])),
              fmaxf(fmaxf(red[4], red[5]), fmaxf(red[6], red[7])));
    float ex = expf(v.x - m), ey = expf(v.y - m);
    float s = ex + ey;
#pragma unroll
    for (int o = 16; o; o >>= 1) s += __shfl_xor_sync(0xffffffffu, s, o);
    __syncthreads();
    if ((t & 31) == 0) red[t >> 5] = s;
    __syncthreads();
    s = red[0] + red[1] + red[2] + red[3] + red[4] + red[5] + red[6] + red[7];
    float inv = 1.0f / s;
    q[t] = __float22bfloat162_rn(make_float2(ex * inv, ey * inv));
}

// ======================================================================
// layernorm over D=768 (fp32 in -> bf16 out)
// ======================================================================
__global__ void layernorm_k(const float* __restrict__ y, __nv_bfloat16* __restrict__ x)
{
    __shared__ float rs[8], rq[8];
    size_t row = blockIdx.x;
    const float* yp = y + row * DD;
    __nv_bfloat16* xp = x + row * DD;
    int t = threadIdx.x;
    float a0 = yp[t], a1 = yp[t + 256], a2 = yp[t + 512];
    float s = a0 + a1 + a2;
    float q = a0 * a0 + a1 * a1 + a2 * a2;
#pragma unroll
    for (int o = 16; o; o >>= 1) {
        s += __shfl_xor_sync(0xffffffffu, s, o);
        q += __shfl_xor_sync(0xffffffffu, q, o);
    }
    if ((t & 31) == 0) { rs[t >> 5] = s; rq[t >> 5] = q; }
    __syncthreads();
    s = rs[0] + rs[1] + rs[2] + rs[3] + rs[4] + rs[5] + rs[6] + rs[7];
    q = rq[0] + rq[1] + rq[2] + rq[3] + rq[4] + rq[5] + rq[6] + rq[7];
    float mean = s * (1.0f / (float)DD);
    float var  = q * (1.0f / (float)DD) - mean * mean;
    float r = rsqrtf(var + 1e-5f);
    xp[t]       = __float2bfloat16((a0 - mean) * r);
    xp[t + 256] = __float2bfloat16((a1 - mean) * r);
    xp[t + 512] = __float2bfloat16((a2 - mean) * r);
}

// ======================================================================
// gather masked rows (bf16 -> bf16)
// ======================================================================
__global__ void gather_k(const __nv_bfloat16* __restrict__ x, const int* __restrict__ idx,
                         __nv_bfloat16* __restrict__ g)
{
    int r = blockIdx.x;
    int b = r >> 6;
    int s = idx[r];
    const __nv_bfloat16* src = x + ((size_t)(b * SS + s)) * DD;
    __nv_bfloat16* dst = g + (size_t)r * DD;
    for (int d = threadIdx.x; d < DD; d += blockDim.x) dst[d] = src[d];
}

// ======================================================================
// in-place log_softmax over V=30000
// ======================================================================
__global__ void logsoftmax_k(float* __restrict__ out)
{
    __shared__ float red[8];
    size_t row = blockIdx.x;
    float* p = out + row * (size_t)VV;
    int t = threadIdx.x;

    float m = -1e30f;
    for (int j = t; j < VV; j += 256) m = fmaxf(m, p[j]);
#pragma unroll
    for (int o = 16; o; o >>= 1) m = fmaxf(m, __shfl_xor_sync(0xffffffffu, m, o));
    if ((t & 31) == 0) red[t >> 5] = m;
    __syncthreads();
    m = fmaxf(fmaxf(fmaxf(red[0], red[1]), fmaxf(red[2], red[3])),
              fmaxf(fmaxf(red[4], red[5]), fmaxf(red[6], red[7])));

    float s = 0.f;
    for (int j = t; j < VV; j += 256) s += expf(p[j] - m);
#pragma unroll
    for (int o = 16; o; o >>= 1) s += __shfl_xor_sync(0xffffffffu, s, o);
    __syncthreads();
    if ((t & 31) == 0) red[t >> 5] = s;
    __syncthreads();
    s = red[0] + red[1] + red[2] + red[3] + red[4] + red[5] + red[6] + red[7];

    float lse = m + logf(s);
    for (int j = t; j < VV; j += 256) p[j] = p[j] - lse;
}

// ======================================================================
// launcher
// ======================================================================
extern "C" void kernel_launch(void* const* d_in, const int* in_sizes, int n_in,
                              void* d_out, int out_size)
{
    (void)in_sizes; (void)n_in; (void)out_size;
    const float* onehot = (const float*)d_in[0];
    const float* se_w = (const float*)d_in[1];
    const float* se_b = (const float*)d_in[2];
    const float* wq = (const float*)d_in[3];  const float* bq = (const float*)d_in[4];
    const float* wk = (const float*)d_in[5];  const float* bk = (const float*)d_in[6];
    const float* wv = (const float*)d_in[7];  const float* bv = (const float*)d_in[8];
    const float* wo = (const float*)d_in[9];  const float* bo = (const float*)d_in[10];
    const float* w1 = (const float*)d_in[11]; const float* b1 = (const float*)d_in[12];
    const float* w2 = (const float*)d_in[13]; const float* b2 = (const float*)d_in[14];
    const float* we = (const float*)d_in[15]; const float* be = (const float*)d_in[16];
    const int*   idx = (const int*)d_in[17];
    float* out = (float*)d_out;

    float *px, *py, *patt, *pbqkv;
    __nv_bfloat16 *pxb, *plnb, *pob, *pqb, *pkb, *pvtb, *pattb, *ph1b, *pgb;
    __nv_bfloat16 *pwqkv, *pwow, *pw1w, *pw2w, *pwew;
    int* ptok;
    cudaGetSymbolAddress((void**)&px,    g_x);
    cudaGetSymbolAddress((void**)&py,    g_y);
    cudaGetSymbolAddress((void**)&patt,  g_att);
    cudaGetSymbolAddress((void**)&pbqkv, g_bqkv);
    cudaGetSymbolAddress((void**)&pxb,   g_xb);
    cudaGetSymbolAddress((void**)&plnb,  g_lnb);
    cudaGetSymbolAddress((void**)&pob,   g_ob);
    cudaGetSymbolAddress((void**)&pqb,   g_qb);
    cudaGetSymbolAddress((void**)&pkb,   g_kb);
    cudaGetSymbolAddress((void**)&pvtb,  g_vtb);
    cudaGetSymbolAddress((void**)&pattb, g_attb);
    cudaGetSymbolAddress((void**)&ph1b,  g_h1b);
    cudaGetSymbolAddress((void**)&pgb,   g_gb);
    cudaGetSymbolAddress((void**)&pwqkv, g_wqkv);
    cudaGetSymbolAddress((void**)&pwow,  g_wow);
    cudaGetSymbolAddress((void**)&pw1w,  g_w1w);
    cudaGetSymbolAddress((void**)&pw2w,  g_w2w);
    cudaGetSymbolAddress((void**)&pwew,  g_wew);
    cudaGetSymbolAddress((void**)&ptok,  g_tok);

    const int SM128 = 2 * 16384 + 2 * 16384;   // 65536
    const int SM64  = 2 * 16384 + 2 * 8192;    // 49152
    cudaFuncSetAttribute(tgemm_k<EP_QKV,  128>, cudaFuncAttributeMaxDynamicSharedMemorySize, SM128);
    cudaFuncSetAttribute(tgemm_k<EP_SCORE,128>, cudaFuncAttributeMaxDynamicSharedMemorySize, SM128);
    cudaFuncSetAttribute(tgemm_k<EP_ATTV,  64>, cudaFuncAttributeMaxDynamicSharedMemorySize, SM64);
    cudaFuncSetAttribute(tgemm_k<EP_OPROJ,128>, cudaFuncAttributeMaxDynamicSharedMemorySize, SM128);
    cudaFuncSetAttribute(tgemm_k<EP_FFN1, 128>, cudaFuncAttributeMaxDynamicSharedMemorySize, SM128);
    cudaFuncSetAttribute(tgemm_k<EP_FFN2, 128>, cudaFuncAttributeMaxDynamicSharedMemorySize, SM128);
    cudaFuncSetAttribute(tgemm_k<EP_HEAD, 128>, cudaFuncAttributeMaxDynamicSharedMemorySize, SM128);

    // ---- weight/bias packing (bf16, [N,K]) ----
    dim3 tb(32, 8);
    packb_k<<<9, 256>>>(bq, bk, bv, pbqkv);
    packT_k<<<dim3(24, 24), tb>>>(wq, pwqkv,               DD, DD, DD);
    packT_k<<<dim3(24, 24), tb>>>(wk, pwqkv + DD * DD,     DD, DD, DD);
    packT_k<<<dim3(24, 24), tb>>>(wv, pwqkv + 2 * DD * DD, DD, DD, DD);
    packT_k<<<dim3(24, 24), tb>>>(wo, pwow,                DD, DD, DD);
    packT_k<<<dim3(96, 24), tb>>>(w1, pw1w,                DD, FF_, FF_);
    packT_k<<<dim3(24, 96), tb>>>(w2, pw2w,                FF_, DD, DD);
    packT_k<<<dim3(940, 24), tb>>>(we, pwew,               DD, VV, VPAD);

    // ---- embedding ----
    findtok_k<<<BB * SS, 256>>>(onehot, ptok);
    embed_k<<<BB * SS, 256>>>(se_w, se_b, ptok, px, pxb);

    const long long sQK = (long long)SS * DH;    // per-(b,h) stride in qb/kb/vtb
    const long long sAT = (long long)SS * SS;    // per-(b,h) stride in att

    for (int l = 0; l < NLAYERS; l++) {
        // QKV fused: [2048,768] @ [2304,768]^T
        tgemm_k<EP_QKV, 128><<<dim3(18, 16, 1), 256, SM128>>>(
            pxb, pwqkv, DD, DD, DD, 0, 0, pbqkv, nullptr);

        // scores: 48 x [512,64] @ [512,64]^T, *0.125 -> fp32 att
        tgemm_k<EP_SCORE, 128><<<dim3(4, 4, BB * HH), 256, SM128>>>(
            pqb, pkb, DH, DH, DH, sQK, sQK, nullptr, nullptr);

        softmax_k<<<BB * HH * SS, 256>>>(patt, pattb);

        // att @ V: 48 x [512,512] @ [64,512]^T -> ob (concat heads)
        tgemm_k<EP_ATTV, 64><<<dim3(1, 4, BB * HH), 256, SM64>>>(
            pattb, pvtb, SS, SS, SS, sAT, sQK, nullptr, nullptr);

        // o @ wo + bo + x -> y (fp32)
        tgemm_k<EP_OPROJ, 128><<<dim3(6, 16, 1), 256, SM128>>>(
            pob, pwow, DD, DD, DD, 0, 0, bo, nullptr);

        layernorm_k<<<BB * SS, 256>>>(py, plnb);

        // relu(ln @ w1 + b1) -> h1b (bf16)
        tgemm_k<EP_FFN1, 128><<<dim3(24, 16, 1), 256, SM128>>>(
            plnb, pw1w, DD, DD, DD, 0, 0, b1, nullptr);

        // h1 @ w2 + b2 -> x (fp32) + xb (bf16)
        tgemm_k<EP_FFN2, 128><<<dim3(6, 16, 1), 256, SM128>>>(
            ph1b, pw2w, FF_, FF_, FF_, 0, 0, b2, nullptr);
    }

    // gather + vocab head + log_softmax
    gather_k<<<BB * MM, 256>>>(pxb, idx, pgb);
    tgemm_k<EP_HEAD, 128><<<dim3(VPAD / 128, 2, 1), 256, SM128>>>(
        pgb, pwew, DD, DD, DD, 0, 0, be, out);
    logsoftmax_k<<<BB * MM, 256>>>(out);
}

// round 11
// speedup vs baseline: 6.0495x; 1.1920x over previous
#include <cuda_runtime.h>
#include <cuda_bf16.h>
#include <math.h>

// ---------------- problem constants ----------------
#define BB 4
#define SS 512
#define DD 768
#define FF_ 3072
#define VV 30000
#define VPAD 30080
#define HH 12
#define MM 64
#define DH 64
#define NLAYERS 12

// ---------------- static device scratch ----------------
__device__ float g_x  [BB*SS*DD];
__device__ float g_y  [BB*SS*DD];
__device__ float g_bqkv[3*DD];
__device__ __nv_bfloat16 g_xb  [BB*SS*DD];
__device__ __nv_bfloat16 g_lnb [BB*SS*DD];
__device__ __nv_bfloat16 g_ob  [BB*SS*DD];
__device__ __nv_bfloat16 g_qb  [BB*HH*SS*DH];
__device__ __nv_bfloat16 g_kb  [BB*HH*SS*DH];
__device__ __nv_bfloat16 g_vtb [BB*HH*DH*SS];
__device__ __nv_bfloat16 g_h1b [BB*SS*FF_];
__device__ __nv_bfloat16 g_gb  [BB*MM*DD];
__device__ __nv_bfloat16 g_wqkv[3*DD*DD];   // [n=2304][k=768]
__device__ __nv_bfloat16 g_wow [DD*DD];     // [n][k]
__device__ __nv_bfloat16 g_w1w [FF_*DD];    // [3072][768]
__device__ __nv_bfloat16 g_w2w [DD*FF_];    // [768][3072]
__device__ __nv_bfloat16 g_wew [VPAD*DD];   // [30080][768], rows >= 30000 zero
__device__ int g_tok[BB*SS];

// ====================== PTX helpers (arch-portable) ====================
__device__ __forceinline__ unsigned smem_u32(const void* p) {
    unsigned a;
    asm("{ .reg .u64 t; cvta.to.shared.u64 t, %1; cvt.u32.u64 %0, t; }" : "=r"(a) : "l"(p));
    return a;
}
#define SWZ(off) ((unsigned)(off) ^ (((unsigned)(off) >> 3) & 0x70u))

#define CP_ASYNC16(dst, src) \
    asm volatile("cp.async.cg.shared.global [%0], [%1], 16;" :: "r"(dst), "l"(src))
#define CP_COMMIT() asm volatile("cp.async.commit_group;" ::: "memory")
#define CP_WAIT2()  asm volatile("cp.async.wait_group 2;" ::: "memory")
#define CP_WAIT1()  asm volatile("cp.async.wait_group 1;" ::: "memory")
#define CP_WAIT0()  asm volatile("cp.async.wait_group 0;" ::: "memory")

#define LDSM4(r, addr) \
    asm volatile("ldmatrix.sync.aligned.m8n8.x4.shared.b16 {%0,%1,%2,%3}, [%4];" \
        : "=r"((r)[0]), "=r"((r)[1]), "=r"((r)[2]), "=r"((r)[3]) : "r"(addr))

#define MMA16816(c, a, b0, b1) \
    asm volatile("mma.sync.aligned.m16n8k16.row.col.f32.bf16.bf16.f32 " \
        "{%0,%1,%2,%3}, {%4,%5,%6,%7}, {%8,%9}, {%0,%1,%2,%3};" \
        : "+f"((c)[0]), "+f"((c)[1]), "+f"((c)[2]), "+f"((c)[3]) \
        : "r"((a)[0]), "r"((a)[1]), "r"((a)[2]), "r"((a)[3]), "r"(b0), "r"(b1))

__device__ __forceinline__ unsigned pack_bf16x2(float lo, float hi) {
    __nv_bfloat162 h = __float22bfloat162_rn(make_float2(lo, hi));
    return *(unsigned*)&h;
}

// ---------------- epilogue modes ----------------
#define EP_QKV   0
#define EP_OPROJ 1
#define EP_FFN1  2
#define EP_FFN2  3
#define EP_HEAD  4

template<int EPI>
__device__ __forceinline__ void epi_store(int r, int c, float v,
                                          const float* __restrict__ bias,
                                          float* __restrict__ outp)
{
    if (EPI == EP_QKV) {
        int b = r >> 9, s = r & 511;
        float val = v + bias[c];
        int which = c / DD, rr = c - which * DD, h = rr >> 6, d = rr & 63;
        __nv_bfloat16 bv = __float2bfloat16(val);
        if (which == 2)
            g_vtb[((size_t)(b * HH + h) * DH + d) * SS + s] = bv;
        else {
            size_t base = ((size_t)(b * HH + h) * SS + s) * DH + d;
            if (which == 0) g_qb[base] = bv; else g_kb[base] = bv;
        }
    } else if (EPI == EP_OPROJ) {
        size_t off = (size_t)r * DD + c;
        g_y[off] = v + bias[c] + g_x[off];
    } else if (EPI == EP_FFN1) {
        g_h1b[(size_t)r * FF_ + c] = __float2bfloat16(fmaxf(v + bias[c], 0.f));
    } else if (EPI == EP_FFN2) {
        size_t off = (size_t)r * DD + c;
        float val = v + bias[c];
        g_x[off]  = val;
        g_xb[off] = __float2bfloat16(val);
    } else { // EP_HEAD
        if (c < VV) outp[(size_t)r * VV + c] = v + bias[c];
    }
}

// ======================================================================
// bf16 mma.sync GEMM:  D[128 x 128] = A_tile @ B_tile^T  (fp32 accum)
// A: [M,K] bf16 K-major (lda).  B: [N,K] bf16 K-major (ldb).
// Grid: (N/128, M/128).  K multiple of 64.  BK=64, 3-stage cp.async,
// SW128-swizzled smem, ldmatrix.x4 fragments, fused per-mode epilogue.
// ======================================================================
template<int EPI>
__global__ void __launch_bounds__(256)
tgemm_k(const __nv_bfloat16* __restrict__ A, const __nv_bfloat16* __restrict__ B,
        int K, int lda, int ldb,
        const float* __restrict__ bias, float* __restrict__ outp)
{
    extern __shared__ char dsm[];
    constexpr int ABUF = 128 * 128;     // 16 KB
    constexpr int BBUF = 128 * 128;     // 16 KB

    const int tid  = threadIdx.x;
    const int lane = tid & 31, wid = tid >> 5;
    const int wm = wid & 3, wn = wid >> 2;            // 4 x 2 warp grid
    const int m0 = blockIdx.y * 128, n0 = blockIdx.x * 128;
    const unsigned sb = smem_u32(dsm);

    A += (size_t)m0 * lda;
    B += (size_t)n0 * ldb;

    const int NC = K >> 6;

    float acc[2][8][4];
#pragma unroll
    for (int i = 0; i < 2; i++)
#pragma unroll
        for (int j = 0; j < 8; j++)
#pragma unroll
            for (int k = 0; k < 4; k++) acc[i][j][k] = 0.f;

    auto load_chunk = [&](int kc, int buf) {
        const __nv_bfloat16* Ap = A + kc * 64;
        unsigned ab = sb + buf * ABUF;
#pragma unroll
        for (int i = 0; i < 4; i++) {
            int ch = tid + i * 256;
            int row = ch >> 3, c = ch & 7;
            CP_ASYNC16(ab + SWZ(row * 128 + c * 16), Ap + (size_t)row * lda + c * 8);
        }
        const __nv_bfloat16* Bp = B + kc * 64;
        unsigned bb = sb + 3 * ABUF + buf * BBUF;
#pragma unroll
        for (int i = 0; i < 4; i++) {
            int ch = tid + i * 256;
            int row = ch >> 3, c = ch & 7;
            CP_ASYNC16(bb + SWZ(row * 128 + c * 16), Bp + (size_t)row * ldb + c * 8);
        }
    };

    load_chunk(0, 0); CP_COMMIT();
    if (NC > 1) load_chunk(1, 1);
    CP_COMMIT();

    const int a_row = (lane & 15);
    const int a_half = (lane >> 4);
    const int b_noff = (lane & 7) + ((lane >> 4) << 3);
    const int b_half = (lane >> 3) & 1;

    for (int kc = 0; kc < NC; kc++) {
        const int buf = kc % 3;
        if (kc + 2 < NC) load_chunk(kc + 2, (kc + 2) % 3);
        CP_COMMIT();
        CP_WAIT2();
        __syncthreads();

        const unsigned ab = sb + buf * ABUF;
        const unsigned bb = sb + 3 * ABUF + buf * BBUF;
#pragma unroll
        for (int ks = 0; ks < 4; ks++) {
            unsigned a[2][4];
#pragma unroll
            for (int mt = 0; mt < 2; mt++) {
                int row = wm * 32 + mt * 16 + a_row;
                LDSM4(a[mt], ab + SWZ(row * 128 + ks * 32 + a_half * 16));
            }
#pragma unroll
            for (int ntp = 0; ntp < 4; ntp++) {
                unsigned b[4];
                int nrow = wn * 64 + ntp * 16 + b_noff;
                LDSM4(b, bb + SWZ(nrow * 128 + ks * 32 + b_half * 16));
#pragma unroll
                for (int mt = 0; mt < 2; mt++) {
                    MMA16816(acc[mt][2 * ntp],     a[mt], b[0], b[1]);
                    MMA16816(acc[mt][2 * ntp + 1], a[mt], b[2], b[3]);
                }
            }
        }
        __syncthreads();
    }

    // ---- epilogue ----
    const int g = lane >> 2, t = lane & 3;
#pragma unroll
    for (int mt = 0; mt < 2; mt++) {
#pragma unroll
        for (int nt = 0; nt < 8; nt++) {
            int r0 = m0 + wm * 32 + mt * 16 + g;
            int c0 = n0 + wn * 64 + nt * 8 + t * 2;
            epi_store<EPI>(r0,     c0,     acc[mt][nt][0], bias, outp);
            epi_store<EPI>(r0,     c0 + 1, acc[mt][nt][1], bias, outp);
            epi_store<EPI>(r0 + 8, c0,     acc[mt][nt][2], bias, outp);
            epi_store<EPI>(r0 + 8, c0 + 1, acc[mt][nt][3], bias, outp);
        }
    }
}

// ======================================================================
// Fused attention: per CTA one (b,h) and 64 query rows.
// S = scale * Q Kc^T (mma), online softmax in regs, O += P Vc (mma).
// Q:[S,DH] K:[S,DH] bf16 K-major; Vt:[DH,S] bf16 (so Vt is B=[n=dh][k=seq]).
// Block 128 threads (4 warps x 16 rows). K/V chunks of 128, double buffer.
// ======================================================================
__global__ void __launch_bounds__(128)
fattn_k()
{
    extern __shared__ char dsm[];
    const unsigned sb = smem_u32(dsm);
    const int tid = threadIdx.x, lane = tid & 31, w = tid >> 5;
    const int z = blockIdx.y;
    const int b = z / HH, h = z - b * HH;
    const int q0 = blockIdx.x * 64;

    const __nv_bfloat16* Q  = g_qb  + (size_t)z * SS * DH + (size_t)q0 * DH;
    const __nv_bfloat16* Kp = g_kb  + (size_t)z * SS * DH;
    const __nv_bfloat16* Vt = g_vtb + (size_t)z * DH * SS;

    const unsigned QS = sb;                 // 8 KB
    const unsigned KS = sb + 8192;          // 2 x 16 KB
    const unsigned VS = sb + 8192 + 32768;  // 2 x 16 KB (two 8 KB k-slabs each)

    // Q tile: 64 rows x 64 bf16
#pragma unroll
    for (int i = 0; i < 4; i++) {
        int ch = tid + i * 128, row = ch >> 3, c = ch & 7;
        CP_ASYNC16(QS + SWZ(row * 128 + c * 16), Q + (size_t)row * DH + c * 8);
    }
    auto loadKV = [&](int kc, int buf) {
        const __nv_bfloat16* Kc = Kp + (size_t)(kc * 128) * DH;
        unsigned kb = KS + buf * 16384;
#pragma unroll
        for (int i = 0; i < 8; i++) {
            int ch = tid + i * 128, row = ch >> 3, c = ch & 7;
            CP_ASYNC16(kb + SWZ(row * 128 + c * 16), Kc + (size_t)row * DH + c * 8);
        }
        unsigned vb = VS + buf * 16384;
#pragma unroll
        for (int i = 0; i < 8; i++) {
            int ch = tid + i * 128, row = ch >> 4, c = ch & 15;
            int slab = c >> 3;
            CP_ASYNC16(vb + slab * 8192 + SWZ(row * 128 + (c & 7) * 16),
                       Vt + (size_t)row * SS + kc * 128 + c * 8);
        }
    };
    loadKV(0, 0); CP_COMMIT();
    loadKV(1, 1); CP_COMMIT();

    float oacc[8][4];
#pragma unroll
    for (int j = 0; j < 8; j++)
#pragma unroll
        for (int k = 0; k < 4; k++) oacc[j][k] = 0.f;
    float m0 = -1e30f, m1 = -1e30f, l0 = 0.f, l1 = 0.f;

    const int a_row = (lane & 15), a_half = (lane >> 4);
    const int b_noff = (lane & 7) + ((lane >> 4) << 3), b_half = (lane >> 3) & 1;
    const int g = lane >> 2, t4 = lane & 3;

    for (int kc = 0; kc < 4; kc++) {
        if (kc < 3) CP_WAIT1(); else CP_WAIT0();
        __syncthreads();
        const unsigned kb = KS + (kc & 1) * 16384;
        const unsigned vb = VS + (kc & 1) * 16384;

        // ---- S = Q @ Kc^T : 16 rows x 128 cols per warp ----
        float sacc[16][4];
#pragma unroll
        for (int j = 0; j < 16; j++)
#pragma unroll
            for (int k = 0; k < 4; k++) sacc[j][k] = 0.f;
#pragma unroll
        for (int ks = 0; ks < 4; ks++) {
            unsigned aq[4];
            LDSM4(aq, QS + SWZ((w * 16 + a_row) * 128 + ks * 32 + a_half * 16));
#pragma unroll
            for (int ntp = 0; ntp < 8; ntp++) {
                unsigned bk[4];
                LDSM4(bk, kb + SWZ((ntp * 16 + b_noff) * 128 + ks * 32 + b_half * 16));
                MMA16816(sacc[2 * ntp],     aq, bk[0], bk[1]);
                MMA16816(sacc[2 * ntp + 1], aq, bk[2], bk[3]);
            }
        }
        // ---- online softmax (rows g and g+8 of this warp tile) ----
        float mx0 = -1e30f, mx1 = -1e30f;
#pragma unroll
        for (int j = 0; j < 16; j++) {
            sacc[j][0] *= 0.125f; sacc[j][1] *= 0.125f;
            sacc[j][2] *= 0.125f; sacc[j][3] *= 0.125f;
            mx0 = fmaxf(mx0, fmaxf(sacc[j][0], sacc[j][1]));
            mx1 = fmaxf(mx1, fmaxf(sacc[j][2], sacc[j][3]));
        }
        mx0 = fmaxf(mx0, __shfl_xor_sync(0xffffffffu, mx0, 1));
        mx0 = fmaxf(mx0, __shfl_xor_sync(0xffffffffu, mx0, 2));
        mx1 = fmaxf(mx1, __shfl_xor_sync(0xffffffffu, mx1, 1));
        mx1 = fmaxf(mx1, __shfl_xor_sync(0xffffffffu, mx1, 2));
        float nm0 = fmaxf(m0, mx0), nm1 = fmaxf(m1, mx1);
        float al0 = expf(m0 - nm0), al1 = expf(m1 - nm1);
        m0 = nm0; m1 = nm1;
        float rs0 = 0.f, rs1 = 0.f;
#pragma unroll
        for (int j = 0; j < 16; j++) {
            sacc[j][0] = expf(sacc[j][0] - m0); sacc[j][1] = expf(sacc[j][1] - m0);
            sacc[j][2] = expf(sacc[j][2] - m1); sacc[j][3] = expf(sacc[j][3] - m1);
            rs0 += sacc[j][0] + sacc[j][1];
            rs1 += sacc[j][2] + sacc[j][3];
        }
        rs0 += __shfl_xor_sync(0xffffffffu, rs0, 1);
        rs0 += __shfl_xor_sync(0xffffffffu, rs0, 2);
        rs1 += __shfl_xor_sync(0xffffffffu, rs1, 1);
        rs1 += __shfl_xor_sync(0xffffffffu, rs1, 2);
        l0 = l0 * al0 + rs0;
        l1 = l1 * al1 + rs1;
#pragma unroll
        for (int j = 0; j < 8; j++) {
            oacc[j][0] *= al0; oacc[j][1] *= al0;
            oacc[j][2] *= al1; oacc[j][3] *= al1;
        }
        // ---- O += P @ Vc : P (C-frag) -> A-frag bf16x2 identity ----
#pragma unroll
        for (int ksl = 0; ksl < 8; ksl++) {
            unsigned pa[4];
            pa[0] = pack_bf16x2(sacc[2 * ksl][0],     sacc[2 * ksl][1]);
            pa[1] = pack_bf16x2(sacc[2 * ksl][2],     sacc[2 * ksl][3]);
            pa[2] = pack_bf16x2(sacc[2 * ksl + 1][0], sacc[2 * ksl + 1][1]);
            pa[3] = pack_bf16x2(sacc[2 * ksl + 1][2], sacc[2 * ksl + 1][3]);
            int slab = ksl >> 2, ks2 = ksl & 3;
#pragma unroll
            for (int ntp = 0; ntp < 4; ntp++) {
                unsigned bv[4];
                LDSM4(bv, vb + slab * 8192 + SWZ((ntp * 16 + b_noff) * 128 + ks2 * 32 + b_half * 16));
                MMA16816(oacc[2 * ntp],     pa, bv[0], bv[1]);
                MMA16816(oacc[2 * ntp + 1], pa, bv[2], bv[3]);
            }
        }
        __syncthreads();
        if (kc + 2 < 4) { loadKV(kc + 2, kc & 1); CP_COMMIT(); }
    }

    // ---- normalize and write O ----
    float inv0 = 1.f / l0, inv1 = 1.f / l1;
    int row0 = q0 + w * 16 + g;
    __nv_bfloat16* Ob = g_ob + (size_t)(b * SS) * DD + h * DH;
#pragma unroll
    for (int j = 0; j < 8; j++) {
        int col = j * 8 + t4 * 2;
        *(__nv_bfloat162*)(Ob + (size_t)row0 * DD + col) =
            __float22bfloat162_rn(make_float2(oacc[j][0] * inv0, oacc[j][1] * inv0));
        *(__nv_bfloat162*)(Ob + (size_t)(row0 + 8) * DD + col) =
            __float22bfloat162_rn(make_float2(oacc[j][2] * inv1, oacc[j][3] * inv1));
    }
}

// ======================================================================
// weight transpose+pack: src fp32 [K,N] -> dst bf16 [Npad,K] (64x64 tiles)
// ======================================================================
__global__ void __launch_bounds__(256)
packT_k(const float* __restrict__ src, __nv_bfloat16* __restrict__ dst,
        int K, int N, int Npad)
{
    __shared__ float ts[64][65];
    int n0 = blockIdx.x * 64, k0 = blockIdx.y * 64;
    int t = threadIdx.x;
    int kr = t >> 2, cq = t & 3;
#pragma unroll
    for (int i = 0; i < 4; i++) {
        int nc = (cq + i * 4) * 4;
        int n = n0 + nc;
        const float* sp = src + (size_t)(k0 + kr) * N;
        float4 v;
        if (n + 3 < N) v = *(const float4*)(sp + n);
        else {
            v.x = (n + 0 < N) ? sp[n + 0] : 0.f;
            v.y = (n + 1 < N) ? sp[n + 1] : 0.f;
            v.z = (n + 2 < N) ? sp[n + 2] : 0.f;
            v.w = (n + 3 < N) ? sp[n + 3] : 0.f;
        }
        ts[kr][nc] = v.x; ts[kr][nc + 1] = v.y; ts[kr][nc + 2] = v.z; ts[kr][nc + 3] = v.w;
    }
    __syncthreads();
    int nr = t >> 2, ks = (t & 3) * 16;
    if (n0 + nr < Npad) {
        unsigned ov[8];
#pragma unroll
        for (int e = 0; e < 8; e++)
            ov[e] = pack_bf16x2(ts[ks + 2 * e][nr], ts[ks + 2 * e + 1][nr]);
        __nv_bfloat16* dp = dst + (size_t)(n0 + nr) * K + k0 + ks;
        *(uint4*)dp       = make_uint4(ov[0], ov[1], ov[2], ov[3]);
        *(uint4*)(dp + 8) = make_uint4(ov[4], ov[5], ov[6], ov[7]);
    }
}

__global__ void packb_k(const float* __restrict__ bq, const float* __restrict__ bk,
                        const float* __restrict__ bv, float* __restrict__ dst)
{
    int i = blockIdx.x * 256 + threadIdx.x;
    if (i < DD) dst[i] = bq[i];
    else if (i < 2 * DD) dst[i] = bk[i - DD];
    else if (i < 3 * DD) dst[i] = bv[i - 2 * DD];
}

// ======================================================================
// one-hot -> token id (float4 scan)
// ======================================================================
__global__ void findtok_k(const float* __restrict__ oh, int* __restrict__ tok)
{
    size_t row = blockIdx.x;
    const float4* r = (const float4*)(oh + row * (size_t)VV);
    for (int j = threadIdx.x; j < VV / 4; j += blockDim.x) {
        float4 v = r[j];
        if (v.x > 0.5f) tok[row] = 4 * j;
        else if (v.y > 0.5f) tok[row] = 4 * j + 1;
        else if (v.z > 0.5f) tok[row] = 4 * j + 2;
        else if (v.w > 0.5f) tok[row] = 4 * j + 3;
    }
}

// ======================================================================
// x = se_w[tok] + se_b + positional encoding ; also bf16 mirror
// ======================================================================
__global__ void embed_k(const float* __restrict__ se_w, const float* __restrict__ se_b,
                        const int* __restrict__ tok, float* __restrict__ x,
                        __nv_bfloat16* __restrict__ xb)
{
    int row = blockIdx.x;
    int s   = row & (SS - 1);
    int tk  = tok[row];
    const float* wrow = se_w + (size_t)tk * DD;
    float* xr = x + (size_t)row * DD;
    __nv_bfloat16* xbr = xb + (size_t)row * DD;
    for (int d = threadIdx.x; d < DD; d += blockDim.x) {
        float pe = 0.f;
        if (s != 0) {
            float denom = powf(10000.0f, (2.0f * (float)d) / (float)DD);
            float raw   = (float)s / denom;
            pe = (d & 1) ? cosf(raw) : sinf(raw);
        }
        float v = wrow[d] + se_b[d] + pe;
        xr[d] = v;
        xbr[d] = __float2bfloat16(v);
    }
}

// ======================================================================
// layernorm over D=768 (fp32 in -> bf16 out)
// ======================================================================
__global__ void layernorm_k(const float* __restrict__ y, __nv_bfloat16* __restrict__ x)
{
    __shared__ float rs[8], rq[8];
    size_t row = blockIdx.x;
    const float* yp = y + row * DD;
    __nv_bfloat16* xp = x + row * DD;
    int t = threadIdx.x;
    float a0 = yp[t], a1 = yp[t + 256], a2 = yp[t + 512];
    float s = a0 + a1 + a2;
    float q = a0 * a0 + a1 * a1 + a2 * a2;
#pragma unroll
    for (int o = 16; o; o >>= 1) {
        s += __shfl_xor_sync(0xffffffffu, s, o);
        q += __shfl_xor_sync(0xffffffffu, q, o);
    }
    if ((t & 31) == 0) { rs[t >> 5] = s; rq[t >> 5] = q; }
    __syncthreads();
    s = rs[0] + rs[1] + rs[2] + rs[3] + rs[4] + rs[5] + rs[6] + rs[7];
    q = rq[0] + rq[1] + rq[2] + rq[3] + rq[4] + rq[5] + rq[6] + rq[7];
    float mean = s * (1.0f / (float)DD);
    float var  = q * (1.0f / (float)DD) - mean * mean;
    float r = rsqrtf(var + 1e-5f);
    xp[t]       = __float2bfloat16((a0 - mean) * r);
    xp[t + 256] = __float2bfloat16((a1 - mean) * r);
    xp[t + 512] = __float2bfloat16((a2 - mean) * r);
}

// ======================================================================
// gather masked rows (bf16 -> bf16)
// ======================================================================
__global__ void gather_k(const __nv_bfloat16* __restrict__ x, const int* __restrict__ idx,
                         __nv_bfloat16* __restrict__ g)
{
    int r = blockIdx.x;
    int b = r >> 6;
    int s = idx[r];
    const __nv_bfloat16* src = x + ((size_t)(b * SS + s)) * DD;
    __nv_bfloat16* dst = g + (size_t)r * DD;
    for (int d = threadIdx.x; d < DD; d += blockDim.x) dst[d] = src[d];
}

// ======================================================================
// in-place log_softmax over V=30000
// ======================================================================
__global__ void logsoftmax_k(float* __restrict__ out)
{
    __shared__ float red[8];
    size_t row = blockIdx.x;
    float* p = out + row * (size_t)VV;
    int t = threadIdx.x;

    float m = -1e30f;
    for (int j = t; j < VV; j += 256) m = fmaxf(m, p[j]);
#pragma unroll
    for (int o = 16; o; o >>= 1) m = fmaxf(m, __shfl_xor_sync(0xffffffffu, m, o));
    if ((t & 31) == 0) red[t >> 5] = m;
    __syncthreads();
    m = fmaxf(fmaxf(fmaxf(red[0], red[1]), fmaxf(red[2], red[3])),
              fmaxf(fmaxf(red[4], red[5]), fmaxf(red[6], red[7])));

    float s = 0.f;
    for (int j = t; j < VV; j += 256) s += expf(p[j] - m);
#pragma unroll
    for (int o = 16; o; o >>= 1) s += __shfl_xor_sync(0xffffffffu, s, o);
    __syncthreads();
    if ((t & 31) == 0) red[t >> 5] = s;
    __syncthreads();
    s = red[0] + red[1] + red[2] + red[3] + red[4] + red[5] + red[6] + red[7];

    float lse = m + logf(s);
    for (int j = t; j < VV; j += 256) p[j] = p[j] - lse;
}

// ======================================================================
// launcher
// ======================================================================
extern "C" void kernel_launch(void* const* d_in, const int* in_sizes, int n_in,
                              void* d_out, int out_size)
{
    (void)in_sizes; (void)n_in; (void)out_size;
    const float* onehot = (const float*)d_in[0];
    const float* se_w = (const float*)d_in[1];
    const float* se_b = (const float*)d_in[2];
    const float* wq = (const float*)d_in[3];  const float* bq = (const float*)d_in[4];
    const float* wk = (const float*)d_in[5];  const float* bk = (const float*)d_in[6];
    const float* wv = (const float*)d_in[7];  const float* bv = (const float*)d_in[8];
    const float* wo = (const float*)d_in[9];  const float* bo = (const float*)d_in[10];
    const float* w1 = (const float*)d_in[11]; const float* b1 = (const float*)d_in[12];
    const float* w2 = (const float*)d_in[13]; const float* b2 = (const float*)d_in[14];
    const float* we = (const float*)d_in[15]; const float* be = (const float*)d_in[16];
    const int*   idx = (const int*)d_in[17];
    float* out = (float*)d_out;

    float *px, *py, *pbqkv;
    __nv_bfloat16 *pxb, *plnb, *pob, *pqb, *pkb, *pvtb, *ph1b, *pgb;
    __nv_bfloat16 *pwqkv, *pwow, *pw1w, *pw2w, *pwew;
    int* ptok;
    cudaGetSymbolAddress((void**)&px,    g_x);
    cudaGetSymbolAddress((void**)&py,    g_y);
    cudaGetSymbolAddress((void**)&pbqkv, g_bqkv);
    cudaGetSymbolAddress((void**)&pxb,   g_xb);
    cudaGetSymbolAddress((void**)&plnb,  g_lnb);
    cudaGetSymbolAddress((void**)&pob,   g_ob);
    cudaGetSymbolAddress((void**)&pqb,   g_qb);
    cudaGetSymbolAddress((void**)&pkb,   g_kb);
    cudaGetSymbolAddress((void**)&pvtb,  g_vtb);
    cudaGetSymbolAddress((void**)&ph1b,  g_h1b);
    cudaGetSymbolAddress((void**)&pgb,   g_gb);
    cudaGetSymbolAddress((void**)&pwqkv, g_wqkv);
    cudaGetSymbolAddress((void**)&pwow,  g_wow);
    cudaGetSymbolAddress((void**)&pw1w,  g_w1w);
    cudaGetSymbolAddress((void**)&pw2w,  g_w2w);
    cudaGetSymbolAddress((void**)&pwew,  g_wew);
    cudaGetSymbolAddress((void**)&ptok,  g_tok);

    const int SMG = 3 * (16384 + 16384);   // 98304: 3-stage A+B
    const int SMA = 8192 + 32768 + 32768;  // 73728: fused attention
    cudaFuncSetAttribute(tgemm_k<EP_QKV>,   cudaFuncAttributeMaxDynamicSharedMemorySize, SMG);
    cudaFuncSetAttribute(tgemm_k<EP_OPROJ>, cudaFuncAttributeMaxDynamicSharedMemorySize, SMG);
    cudaFuncSetAttribute(tgemm_k<EP_FFN1>,  cudaFuncAttributeMaxDynamicSharedMemorySize, SMG);
    cudaFuncSetAttribute(tgemm_k<EP_FFN2>,  cudaFuncAttributeMaxDynamicSharedMemorySize, SMG);
    cudaFuncSetAttribute(tgemm_k<EP_HEAD>,  cudaFuncAttributeMaxDynamicSharedMemorySize, SMG);
    cudaFuncSetAttribute(fattn_k,           cudaFuncAttributeMaxDynamicSharedMemorySize, SMA);

    // ---- weight/bias packing (bf16, [N,K]) ----
    packb_k<<<9, 256>>>(bq, bk, bv, pbqkv);
    packT_k<<<dim3(12, 12), 256>>>(wq, pwqkv,               DD, DD, DD);
    packT_k<<<dim3(12, 12), 256>>>(wk, pwqkv + DD * DD,     DD, DD, DD);
    packT_k<<<dim3(12, 12), 256>>>(wv, pwqkv + 2 * DD * DD, DD, DD, DD);
    packT_k<<<dim3(12, 12), 256>>>(wo, pwow,                DD, DD, DD);
    packT_k<<<dim3(48, 12), 256>>>(w1, pw1w,                DD, FF_, FF_);
    packT_k<<<dim3(12, 48), 256>>>(w2, pw2w,                FF_, DD, DD);
    packT_k<<<dim3(470, 12), 256>>>(we, pwew,               DD, VV, VPAD);

    // ---- embedding ----
    findtok_k<<<BB * SS, 256>>>(onehot, ptok);
    embed_k<<<BB * SS, 256>>>(se_w, se_b, ptok, px, pxb);

    for (int l = 0; l < NLAYERS; l++) {
        // QKV fused: [2048,768] @ [2304,768]^T -> per-head q/k/vt (bf16)
        tgemm_k<EP_QKV><<<dim3(18, 16), 256, SMG>>>(
            pxb, pwqkv, DD, DD, DD, pbqkv, nullptr);

        // fused attention -> g_ob (bf16, heads concatenated)
        fattn_k<<<dim3(SS / 64, BB * HH), 128, SMA>>>();

        // o @ wo + bo + x -> y (fp32)
        tgemm_k<EP_OPROJ><<<dim3(6, 16), 256, SMG>>>(
            pob, pwow, DD, DD, DD, bo, nullptr);

        layernorm_k<<<BB * SS, 256>>>(py, plnb);

        // relu(ln @ w1 + b1) -> h1b (bf16)
        tgemm_k<EP_FFN1><<<dim3(24, 16), 256, SMG>>>(
            plnb, pw1w, DD, DD, DD, b1, nullptr);

        // h1 @ w2 + b2 -> x (fp32) + xb (bf16)
        tgemm_k<EP_FFN2><<<dim3(6, 16), 256, SMG>>>(
            ph1b, pw2w, FF_, FF_, FF_, b2, nullptr);
    }

    // gather + vocab head + log_softmax
    gather_k<<<BB * MM, 256>>>(pxb, idx, pgb);
    tgemm_k<EP_HEAD><<<dim3(VPAD / 128, 2), 256, SMG>>>(
        pgb, pwew, DD, DD, DD, be, out);
    logsoftmax_k<<<BB * MM, 256>>>(out);
}

// round 12
// speedup vs baseline: 7.2807x; 1.2035x over previous
#include <cuda_runtime.h>
#include <cuda_bf16.h>
#include <math.h>

// ---------------- problem constants ----------------
#define BB 4
#define SS 512
#define DD 768
#define FF_ 3072
#define VV 30000
#define VPAD 30080
#define HH 12
#define MM 64
#define DH 64
#define NLAYERS 12

// ---------------- static device scratch ----------------
__device__ float g_x  [BB*SS*DD];
__device__ float g_y  [BB*SS*DD];
__device__ float g_bqkv[3*DD];
__device__ __nv_bfloat16 g_xb  [BB*SS*DD];
__device__ __nv_bfloat16 g_lnb [BB*SS*DD];
__device__ __nv_bfloat16 g_ob  [BB*SS*DD];
__device__ __nv_bfloat16 g_qb  [BB*HH*SS*DH];
__device__ __nv_bfloat16 g_kb  [BB*HH*SS*DH];
__device__ __nv_bfloat16 g_vb  [BB*HH*SS*DH];   // V now K-major like Q/K
__device__ __nv_bfloat16 g_h1b [BB*SS*FF_];
__device__ __nv_bfloat16 g_gb  [BB*MM*DD];
__device__ __nv_bfloat16 g_wqkv[3*DD*DD];   // [n=2304][k=768]
__device__ __nv_bfloat16 g_wow [DD*DD];     // [n][k]
__device__ __nv_bfloat16 g_w1w [FF_*DD];    // [3072][768]
__device__ __nv_bfloat16 g_w2w [DD*FF_];    // [768][3072]
__device__ __nv_bfloat16 g_wew [VPAD*DD];   // [30080][768], rows >= 30000 zero
__device__ int g_tok[BB*SS];

// ====================== PTX helpers (arch-portable) ====================
__device__ __forceinline__ unsigned smem_u32(const void* p) {
    unsigned a;
    asm("{ .reg .u64 t; cvta.to.shared.u64 t, %1; cvt.u32.u64 %0, t; }" : "=r"(a) : "l"(p));
    return a;
}
#define SWZ(off) ((unsigned)(off) ^ (((unsigned)(off) >> 3) & 0x70u))

#define CP_ASYNC16(dst, src) \
    asm volatile("cp.async.cg.shared.global [%0], [%1], 16;" :: "r"(dst), "l"(src))
#define CP_COMMIT() asm volatile("cp.async.commit_group;" ::: "memory")
#define CP_WAIT2()  asm volatile("cp.async.wait_group 2;" ::: "memory")
#define CP_WAIT1()  asm volatile("cp.async.wait_group 1;" ::: "memory")
#define CP_WAIT0()  asm volatile("cp.async.wait_group 0;" ::: "memory")

#define LDSM4(r, addr) \
    asm volatile("ldmatrix.sync.aligned.m8n8.x4.shared.b16 {%0,%1,%2,%3}, [%4];" \
        : "=r"((r)[0]), "=r"((r)[1]), "=r"((r)[2]), "=r"((r)[3]) : "r"(addr))

#define LDSM4T(r, addr) \
    asm volatile("ldmatrix.sync.aligned.m8n8.x4.trans.shared.b16 {%0,%1,%2,%3}, [%4];" \
        : "=r"((r)[0]), "=r"((r)[1]), "=r"((r)[2]), "=r"((r)[3]) : "r"(addr))

#define MMA16816(c, a, b0, b1) \
    asm volatile("mma.sync.aligned.m16n8k16.row.col.f32.bf16.bf16.f32 " \
        "{%0,%1,%2,%3}, {%4,%5,%6,%7}, {%8,%9}, {%0,%1,%2,%3};" \
        : "+f"((c)[0]), "+f"((c)[1]), "+f"((c)[2]), "+f"((c)[3]) \
        : "r"((a)[0]), "r"((a)[1]), "r"((a)[2]), "r"((a)[3]), "r"(b0), "r"(b1))

__device__ __forceinline__ unsigned pack_bf16x2(float lo, float hi) {
    __nv_bfloat162 h = __float22bfloat162_rn(make_float2(lo, hi));
    return *(unsigned*)&h;
}

// ---------------- epilogue modes ----------------
#define EP_QKV   0
#define EP_OPROJ 1
#define EP_FFN1  2
#define EP_FFN2  3
#define EP_HEAD  4

// paired store: columns (c, c+1), c even, same row r
template<int EPI>
__device__ __forceinline__ void epi_store2(int r, int c, float v0, float v1,
                                           const float* __restrict__ bias,
                                           float* __restrict__ outp)
{
    if (EPI == EP_QKV) {
        int b = r >> 9, s = r & 511;
        float a0 = v0 + bias[c], a1 = v1 + bias[c + 1];
        int which = c / DD, rr = c - which * DD, h = rr >> 6, d = rr & 63;
        __nv_bfloat16* dst = (which == 0) ? g_qb : (which == 1) ? g_kb : g_vb;
        unsigned pv = pack_bf16x2(a0, a1);
        *(unsigned*)(dst + ((size_t)(b * HH + h) * SS + s) * DH + d) = pv;
    } else if (EPI == EP_OPROJ) {
        size_t off = (size_t)r * DD + c;
        float2 res = *(const float2*)(g_x + off);
        float2 o = make_float2(v0 + bias[c] + res.x, v1 + bias[c + 1] + res.y);
        *(float2*)(g_y + off) = o;
    } else if (EPI == EP_FFN1) {
        unsigned pv = pack_bf16x2(fmaxf(v0 + bias[c], 0.f), fmaxf(v1 + bias[c + 1], 0.f));
        *(unsigned*)(g_h1b + (size_t)r * FF_ + c) = pv;
    } else if (EPI == EP_FFN2) {
        size_t off = (size_t)r * DD + c;
        float a0 = v0 + bias[c], a1 = v1 + bias[c + 1];
        *(float2*)(g_x + off) = make_float2(a0, a1);
        *(unsigned*)(g_xb + off) = pack_bf16x2(a0, a1);
    } else { // EP_HEAD
        if (c < VV)
            *(float2*)(outp + (size_t)r * VV + c) =
                make_float2(v0 + bias[c], v1 + bias[c + 1]);
    }
}

// ======================================================================
// bf16 mma.sync GEMM:  D[128 x 128] = A_tile @ B_tile^T  (fp32 accum)
// A: [M,K] bf16 K-major (lda).  B: [N,K] bf16 K-major (ldb).
// Grid: (N/128, M/128).  K multiple of 64.  BK=64, 3-stage cp.async,
// SW128-swizzled smem, ldmatrix.x4 fragments, fused per-mode epilogue.
// ======================================================================
template<int EPI>
__global__ void __launch_bounds__(256)
tgemm_k(const __nv_bfloat16* __restrict__ A, const __nv_bfloat16* __restrict__ B,
        int K, int lda, int ldb,
        const float* __restrict__ bias, float* __restrict__ outp)
{
    extern __shared__ char dsm[];
    constexpr int ABUF = 128 * 128;     // 16 KB
    constexpr int BBUF = 128 * 128;     // 16 KB

    const int tid  = threadIdx.x;
    const int lane = tid & 31, wid = tid >> 5;
    const int wm = wid & 3, wn = wid >> 2;            // 4 x 2 warp grid
    const int m0 = blockIdx.y * 128, n0 = blockIdx.x * 128;
    const unsigned sb = smem_u32(dsm);

    A += (size_t)m0 * lda;
    B += (size_t)n0 * ldb;

    const int NC = K >> 6;

    float acc[2][8][4];
#pragma unroll
    for (int i = 0; i < 2; i++)
#pragma unroll
        for (int j = 0; j < 8; j++)
#pragma unroll
            for (int k = 0; k < 4; k++) acc[i][j][k] = 0.f;

    auto load_chunk = [&](int kc, int buf) {
        const __nv_bfloat16* Ap = A + kc * 64;
        unsigned ab = sb + buf * ABUF;
#pragma unroll
        for (int i = 0; i < 4; i++) {
            int ch = tid + i * 256;
            int row = ch >> 3, c = ch & 7;
            CP_ASYNC16(ab + SWZ(row * 128 + c * 16), Ap + (size_t)row * lda + c * 8);
        }
        const __nv_bfloat16* Bp = B + kc * 64;
        unsigned bb = sb + 3 * ABUF + buf * BBUF;
#pragma unroll
        for (int i = 0; i < 4; i++) {
            int ch = tid + i * 256;
            int row = ch >> 3, c = ch & 7;
            CP_ASYNC16(bb + SWZ(row * 128 + c * 16), Bp + (size_t)row * ldb + c * 8);
        }
    };

    load_chunk(0, 0); CP_COMMIT();
    if (NC > 1) load_chunk(1, 1);
    CP_COMMIT();

    const int a_row = (lane & 15);
    const int a_half = (lane >> 4);
    const int b_noff = (lane & 7) + ((lane >> 4) << 3);
    const int b_half = (lane >> 3) & 1;

    for (int kc = 0; kc < NC; kc++) {
        const int buf = kc % 3;
        if (kc + 2 < NC) load_chunk(kc + 2, (kc + 2) % 3);
        CP_COMMIT();
        CP_WAIT2();
        __syncthreads();

        const unsigned ab = sb + buf * ABUF;
        const unsigned bb = sb + 3 * ABUF + buf * BBUF;
#pragma unroll
        for (int ks = 0; ks < 4; ks++) {
            unsigned a[2][4];
#pragma unroll
            for (int mt = 0; mt < 2; mt++) {
                int row = wm * 32 + mt * 16 + a_row;
                LDSM4(a[mt], ab + SWZ(row * 128 + ks * 32 + a_half * 16));
            }
#pragma unroll
            for (int ntp = 0; ntp < 4; ntp++) {
                unsigned b[4];
                int nrow = wn * 64 + ntp * 16 + b_noff;
                LDSM4(b, bb + SWZ(nrow * 128 + ks * 32 + b_half * 16));
#pragma unroll
                for (int mt = 0; mt < 2; mt++) {
                    MMA16816(acc[mt][2 * ntp],     a[mt], b[0], b[1]);
                    MMA16816(acc[mt][2 * ntp + 1], a[mt], b[2], b[3]);
                }
            }
        }
        __syncthreads();
    }

    // ---- epilogue (paired stores: c0,c0+1) ----
    const int g = lane >> 2, t = lane & 3;
#pragma unroll
    for (int mt = 0; mt < 2; mt++) {
#pragma unroll
        for (int nt = 0; nt < 8; nt++) {
            int r0 = m0 + wm * 32 + mt * 16 + g;
            int c0 = n0 + wn * 64 + nt * 8 + t * 2;
            epi_store2<EPI>(r0,     c0, acc[mt][nt][0], acc[mt][nt][1], bias, outp);
            epi_store2<EPI>(r0 + 8, c0, acc[mt][nt][2], acc[mt][nt][3], bias, outp);
        }
    }
}

// ======================================================================
// Fused attention: per CTA one (b,h) and 64 query rows.
// S = scale * Q Kc^T (mma), online softmax in regs, O += P Vc (mma).
// Q,K,V: [z][s][DH] bf16 K-major.  V tile is loaded K-major and the
// transpose for P@V is done by ldmatrix.x4.trans (B fragments).
// Block 128 threads (4 warps x 16 rows). K/V chunks of 128, double buffer.
// ======================================================================
__global__ void __launch_bounds__(128)
fattn_k()
{
    extern __shared__ char dsm[];
    const unsigned sb = smem_u32(dsm);
    const int tid = threadIdx.x, lane = tid & 31, w = tid >> 5;
    const int z = blockIdx.y;
    const int b = z / HH, h = z - b * HH;
    const int q0 = blockIdx.x * 64;

    const __nv_bfloat16* Q  = g_qb + (size_t)z * SS * DH + (size_t)q0 * DH;
    const __nv_bfloat16* Kp = g_kb + (size_t)z * SS * DH;
    const __nv_bfloat16* Vp = g_vb + (size_t)z * SS * DH;

    const unsigned QS = sb;                 // 8 KB
    const unsigned KS = sb + 8192;          // 2 x 16 KB
    const unsigned VS = sb + 8192 + 32768;  // 2 x 16 KB

    // Q tile: 64 rows x 64 bf16
#pragma unroll
    for (int i = 0; i < 4; i++) {
        int ch = tid + i * 128, row = ch >> 3, c = ch & 7;
        CP_ASYNC16(QS + SWZ(row * 128 + c * 16), Q + (size_t)row * DH + c * 8);
    }
    auto loadKV = [&](int kc, int buf) {
        const __nv_bfloat16* Kc = Kp + (size_t)(kc * 128) * DH;
        unsigned kb = KS + buf * 16384;
#pragma unroll
        for (int i = 0; i < 8; i++) {
            int ch = tid + i * 128, row = ch >> 3, c = ch & 7;
            CP_ASYNC16(kb + SWZ(row * 128 + c * 16), Kc + (size_t)row * DH + c * 8);
        }
        const __nv_bfloat16* Vc = Vp + (size_t)(kc * 128) * DH;
        unsigned vb = VS + buf * 16384;
#pragma unroll
        for (int i = 0; i < 8; i++) {
            int ch = tid + i * 128, row = ch >> 3, c = ch & 7;
            CP_ASYNC16(vb + SWZ(row * 128 + c * 16), Vc + (size_t)row * DH + c * 8);
        }
    };
    loadKV(0, 0); CP_COMMIT();
    loadKV(1, 1); CP_COMMIT();

    float oacc[8][4];
#pragma unroll
    for (int j = 0; j < 8; j++)
#pragma unroll
        for (int k = 0; k < 4; k++) oacc[j][k] = 0.f;
    float m0 = -1e30f, m1 = -1e30f, l0 = 0.f, l1 = 0.f;

    const int a_row = (lane & 15), a_half = (lane >> 4);
    const int b_noff = (lane & 7) + ((lane >> 4) << 3), b_half = (lane >> 3) & 1;
    const int g = lane >> 2, t4 = lane & 3;
    // trans-ldmatrix addressing for V ([k-row][n-col] tile):
    const int v_row = (lane & 7) + ((lane >> 3) & 1) * 8;   // k within 16-block
    const int v_col = (lane >> 4) * 16;                     // byte offset (n half)

    for (int kc = 0; kc < 4; kc++) {
        if (kc < 3) CP_WAIT1(); else CP_WAIT0();
        __syncthreads();
        const unsigned kb = KS + (kc & 1) * 16384;
        const unsigned vb = VS + (kc & 1) * 16384;

        // ---- S = Q @ Kc^T : 16 rows x 128 cols per warp ----
        float sacc[16][4];
#pragma unroll
        for (int j = 0; j < 16; j++)
#pragma unroll
            for (int k = 0; k < 4; k++) sacc[j][k] = 0.f;
#pragma unroll
        for (int ks = 0; ks < 4; ks++) {
            unsigned aq[4];
            LDSM4(aq, QS + SWZ((w * 16 + a_row) * 128 + ks * 32 + a_half * 16));
#pragma unroll
            for (int ntp = 0; ntp < 8; ntp++) {
                unsigned bk[4];
                LDSM4(bk, kb + SWZ((ntp * 16 + b_noff) * 128 + ks * 32 + b_half * 16));
                MMA16816(sacc[2 * ntp],     aq, bk[0], bk[1]);
                MMA16816(sacc[2 * ntp + 1], aq, bk[2], bk[3]);
            }
        }
        // ---- online softmax (rows g and g+8 of this warp tile) ----
        float mx0 = -1e30f, mx1 = -1e30f;
#pragma unroll
        for (int j = 0; j < 16; j++) {
            sacc[j][0] *= 0.125f; sacc[j][1] *= 0.125f;
            sacc[j][2] *= 0.125f; sacc[j][3] *= 0.125f;
            mx0 = fmaxf(mx0, fmaxf(sacc[j][0], sacc[j][1]));
            mx1 = fmaxf(mx1, fmaxf(sacc[j][2], sacc[j][3]));
        }
        mx0 = fmaxf(mx0, __shfl_xor_sync(0xffffffffu, mx0, 1));
        mx0 = fmaxf(mx0, __shfl_xor_sync(0xffffffffu, mx0, 2));
        mx1 = fmaxf(mx1, __shfl_xor_sync(0xffffffffu, mx1, 1));
        mx1 = fmaxf(mx1, __shfl_xor_sync(0xffffffffu, mx1, 2));
        float nm0 = fmaxf(m0, mx0), nm1 = fmaxf(m1, mx1);
        float al0 = expf(m0 - nm0), al1 = expf(m1 - nm1);
        m0 = nm0; m1 = nm1;
        float rs0 = 0.f, rs1 = 0.f;
#pragma unroll
        for (int j = 0; j < 16; j++) {
            sacc[j][0] = expf(sacc[j][0] - m0); sacc[j][1] = expf(sacc[j][1] - m0);
            sacc[j][2] = expf(sacc[j][2] - m1); sacc[j][3] = expf(sacc[j][3] - m1);
            rs0 += sacc[j][0] + sacc[j][1];
            rs1 += sacc[j][2] + sacc[j][3];
        }
        rs0 += __shfl_xor_sync(0xffffffffu, rs0, 1);
        rs0 += __shfl_xor_sync(0xffffffffu, rs0, 2);
        rs1 += __shfl_xor_sync(0xffffffffu, rs1, 1);
        rs1 += __shfl_xor_sync(0xffffffffu, rs1, 2);
        l0 = l0 * al0 + rs0;
        l1 = l1 * al1 + rs1;
#pragma unroll
        for (int j = 0; j < 8; j++) {
            oacc[j][0] *= al0; oacc[j][1] *= al0;
            oacc[j][2] *= al1; oacc[j][3] *= al1;
        }
        // ---- O += P @ Vc : P -> A-frag; V via trans-ldmatrix B-frag ----
#pragma unroll
        for (int ksl = 0; ksl < 8; ksl++) {
            unsigned pa[4];
            pa[0] = pack_bf16x2(sacc[2 * ksl][0],     sacc[2 * ksl][1]);
            pa[1] = pack_bf16x2(sacc[2 * ksl][2],     sacc[2 * ksl][3]);
            pa[2] = pack_bf16x2(sacc[2 * ksl + 1][0], sacc[2 * ksl + 1][1]);
            pa[3] = pack_bf16x2(sacc[2 * ksl + 1][2], sacc[2 * ksl + 1][3]);
#pragma unroll
            for (int ntp = 0; ntp < 4; ntp++) {
                unsigned bv[4];
                LDSM4T(bv, vb + SWZ((ksl * 16 + v_row) * 128 + ntp * 32 + v_col));
                MMA16816(oacc[2 * ntp],     pa, bv[0], bv[1]);
                MMA16816(oacc[2 * ntp + 1], pa, bv[2], bv[3]);
            }
        }
        __syncthreads();
        if (kc + 2 < 4) { loadKV(kc + 2, kc & 1); CP_COMMIT(); }
    }

    // ---- normalize and write O ----
    float inv0 = 1.f / l0, inv1 = 1.f / l1;
    int row0 = q0 + w * 16 + g;
    __nv_bfloat16* Ob = g_ob + (size_t)(b * SS) * DD + h * DH;
#pragma unroll
    for (int j = 0; j < 8; j++) {
        int col = j * 8 + t4 * 2;
        *(__nv_bfloat162*)(Ob + (size_t)row0 * DD + col) =
            __float22bfloat162_rn(make_float2(oacc[j][0] * inv0, oacc[j][1] * inv0));
        *(__nv_bfloat162*)(Ob + (size_t)(row0 + 8) * DD + col) =
            __float22bfloat162_rn(make_float2(oacc[j][2] * inv1, oacc[j][3] * inv1));
    }
}

// ======================================================================
// weight transpose+pack: src fp32 [K,N] -> dst bf16 [Npad,K] (64x64 tiles)
// ======================================================================
__global__ void __launch_bounds__(256)
packT_k(const float* __restrict__ src, __nv_bfloat16* __restrict__ dst,
        int K, int N, int Npad)
{
    __shared__ float ts[64][65];
    int n0 = blockIdx.x * 64, k0 = blockIdx.y * 64;
    int t = threadIdx.x;
    int kr = t >> 2, cq = t & 3;
#pragma unroll
    for (int i = 0; i < 4; i++) {
        int nc = (cq + i * 4) * 4;
        int n = n0 + nc;
        const float* sp = src + (size_t)(k0 + kr) * N;
        float4 v;
        if (n + 3 < N) v = *(const float4*)(sp + n);
        else {
            v.x = (n + 0 < N) ? sp[n + 0] : 0.f;
            v.y = (n + 1 < N) ? sp[n + 1] : 0.f;
            v.z = (n + 2 < N) ? sp[n + 2] : 0.f;
            v.w = (n + 3 < N) ? sp[n + 3] : 0.f;
        }
        ts[kr][nc] = v.x; ts[kr][nc + 1] = v.y; ts[kr][nc + 2] = v.z; ts[kr][nc + 3] = v.w;
    }
    __syncthreads();
    int nr = t >> 2, ks = (t & 3) * 16;
    if (n0 + nr < Npad) {
        unsigned ov[8];
#pragma unroll
        for (int e = 0; e < 8; e++)
            ov[e] = pack_bf16x2(ts[ks + 2 * e][nr], ts[ks + 2 * e + 1][nr]);
        __nv_bfloat16* dp = dst + (size_t)(n0 + nr) * K + k0 + ks;
        *(uint4*)dp       = make_uint4(ov[0], ov[1], ov[2], ov[3]);
        *(uint4*)(dp + 8) = make_uint4(ov[4], ov[5], ov[6], ov[7]);
    }
}

__global__ void packb_k(const float* __restrict__ bq, const float* __restrict__ bk,
                        const float* __restrict__ bv, float* __restrict__ dst)
{
    int i = blockIdx.x * 256 + threadIdx.x;
    if (i < DD) dst[i] = bq[i];
    else if (i < 2 * DD) dst[i] = bk[i - DD];
    else if (i < 3 * DD) dst[i] = bv[i - 2 * DD];
}

// ======================================================================
// one-hot -> token id (float4 scan)
// ======================================================================
__global__ void findtok_k(const float* __restrict__ oh, int* __restrict__ tok)
{
    size_t row = blockIdx.x;
    const float4* r = (const float4*)(oh + row * (size_t)VV);
    for (int j = threadIdx.x; j < VV / 4; j += blockDim.x) {
        float4 v = r[j];
        if (v.x > 0.5f) tok[row] = 4 * j;
        else if (v.y > 0.5f) tok[row] = 4 * j + 1;
        else if (v.z > 0.5f) tok[row] = 4 * j + 2;
        else if (v.w > 0.5f) tok[row] = 4 * j + 3;
    }
}

// ======================================================================
// x = se_w[tok] + se_b + positional encoding ; also bf16 mirror
// ======================================================================
__global__ void embed_k(const float* __restrict__ se_w, const float* __restrict__ se_b,
                        const int* __restrict__ tok, float* __restrict__ x,
                        __nv_bfloat16* __restrict__ xb)
{
    int row = blockIdx.x;
    int s   = row & (SS - 1);
    int tk  = tok[row];
    const float* wrow = se_w + (size_t)tk * DD;
    float* xr = x + (size_t)row * DD;
    __nv_bfloat16* xbr = xb + (size_t)row * DD;
    for (int d = threadIdx.x; d < DD; d += blockDim.x) {
        float pe = 0.f;
        if (s != 0) {
            float denom = powf(10000.0f, (2.0f * (float)d) / (float)DD);
            float raw   = (float)s / denom;
            pe = (d & 1) ? cosf(raw) : sinf(raw);
        }
        float v = wrow[d] + se_b[d] + pe;
        xr[d] = v;
        xbr[d] = __float2bfloat16(v);
    }
}

// ======================================================================
// layernorm over D=768 (fp32 in -> bf16 out)
// ======================================================================
__global__ void layernorm_k(const float* __restrict__ y, __nv_bfloat16* __restrict__ x)
{
    __shared__ float rs[8], rq[8];
    size_t row = blockIdx.x;
    const float* yp = y + row * DD;
    __nv_bfloat16* xp = x + row * DD;
    int t = threadIdx.x;
    float a0 = yp[t], a1 = yp[t + 256], a2 = yp[t + 512];
    float s = a0 + a1 + a2;
    float q = a0 * a0 + a1 * a1 + a2 * a2;
#pragma unroll
    for (int o = 16; o; o >>= 1) {
        s += __shfl_xor_sync(0xffffffffu, s, o);
        q += __shfl_xor_sync(0xffffffffu, q, o);
    }
    if ((t & 31) == 0) { rs[t >> 5] = s; rq[t >> 5] = q; }
    __syncthreads();
    s = rs[0] + rs[1] + rs[2] + rs[3] + rs[4] + rs[5] + rs[6] + rs[7];
    q = rq[0] + rq[1] + rq[2] + rq[3] + rq[4] + rq[5] + rq[6] + rq[7];
    float mean = s * (1.0f / (float)DD);
    float var  = q * (1.0f / (float)DD) - mean * mean;
    float r = rsqrtf(var + 1e-5f);
    xp[t]       = __float2bfloat16((a0 - mean) * r);
    xp[t + 256] = __float2bfloat16((a1 - mean) * r);
    xp[t + 512] = __float2bfloat16((a2 - mean) * r);
}

// ======================================================================
// gather masked rows (bf16 -> bf16)
// ======================================================================
__global__ void gather_k(const __nv_bfloat16* __restrict__ x, const int* __restrict__ idx,
                         __nv_bfloat16* __restrict__ g)
{
    int r = blockIdx.x;
    int b = r >> 6;
    int s = idx[r];
    const __nv_bfloat16* src = x + ((size_t)(b * SS + s)) * DD;
    __nv_bfloat16* dst = g + (size_t)r * DD;
    for (int d = threadIdx.x; d < DD; d += blockDim.x) dst[d] = src[d];
}

// ======================================================================
// in-place log_softmax over V=30000 — single gmem read via smem staging
// ======================================================================
__global__ void logsoftmax_k(float* __restrict__ out)
{
    extern __shared__ float buf[];       // 30000 floats = 117.2 KB
    __shared__ float red[8];
    size_t row = blockIdx.x;
    float* p = out + row * (size_t)VV;
    int t = threadIdx.x;

    float m = -1e30f;
    for (int j = t; j < VV / 4; j += 256) {
        float4 v = *(const float4*)(p + 4 * j);
        *(float4*)(buf + 4 * j) = v;
        m = fmaxf(fmaxf(m, fmaxf(v.x, v.y)), fmaxf(v.z, v.w));
    }
#pragma unroll
    for (int o = 16; o; o >>= 1) m = fmaxf(m, __shfl_xor_sync(0xffffffffu, m, o));
    if ((t & 31) == 0) red[t >> 5] = m;
    __syncthreads();
    m = fmaxf(fmaxf(fmaxf(red[0], red[1]), fmaxf(red[2], red[3])),
              fmaxf(fmaxf(red[4], red[5]), fmaxf(red[6], red[7])));

    float s = 0.f;
    for (int j = t; j < VV / 4; j += 256) {
        float4 v = *(const float4*)(buf + 4 * j);
        s += expf(v.x - m) + expf(v.y - m) + expf(v.z - m) + expf(v.w - m);
    }
#pragma unroll
    for (int o = 16; o; o >>= 1) s += __shfl_xor_sync(0xffffffffu, s, o);
    __syncthreads();
    if ((t & 31) == 0) red[t >> 5] = s;
    __syncthreads();
    s = red[0] + red[1] + red[2] + red[3] + red[4] + red[5] + red[6] + red[7];

    float lse = m + logf(s);
    for (int j = t; j < VV / 4; j += 256) {
        float4 v = *(const float4*)(buf + 4 * j);
        *(float4*)(p + 4 * j) = make_float4(v.x - lse, v.y - lse, v.z - lse, v.w - lse);
    }
}

// ======================================================================
// launcher
// ======================================================================
extern "C" void kernel_launch(void* const* d_in, const int* in_sizes, int n_in,
                              void* d_out, int out_size)
{
    (void)in_sizes; (void)n_in; (void)out_size;
    const float* onehot = (const float*)d_in[0];
    const float* se_w = (const float*)d_in[1];
    const float* se_b = (const float*)d_in[2];
    const float* wq = (const float*)d_in[3];  const float* bq = (const float*)d_in[4];
    const float* wk = (const float*)d_in[5];  const float* bk = (const float*)d_in[6];
    const float* wv = (const float*)d_in[7];  const float* bv = (const float*)d_in[8];
    const float* wo = (const float*)d_in[9];  const float* bo = (const float*)d_in[10];
    const float* w1 = (const float*)d_in[11]; const float* b1 = (const float*)d_in[12];
    const float* w2 = (const float*)d_in[13]; const float* b2 = (const float*)d_in[14];
    const float* we = (const float*)d_in[15]; const float* be = (const float*)d_in[16];
    const int*   idx = (const int*)d_in[17];
    float* out = (float*)d_out;

    float *px, *py, *pbqkv;
    __nv_bfloat16 *pxb, *plnb, *pob, *ph1b, *pgb;
    __nv_bfloat16 *pwqkv, *pwow, *pw1w, *pw2w, *pwew;
    int* ptok;
    cudaGetSymbolAddress((void**)&px,    g_x);
    cudaGetSymbolAddress((void**)&py,    g_y);
    cudaGetSymbolAddress((void**)&pbqkv, g_bqkv);
    cudaGetSymbolAddress((void**)&pxb,   g_xb);
    cudaGetSymbolAddress((void**)&plnb,  g_lnb);
    cudaGetSymbolAddress((void**)&pob,   g_ob);
    cudaGetSymbolAddress((void**)&ph1b,  g_h1b);
    cudaGetSymbolAddress((void**)&pgb,   g_gb);
    cudaGetSymbolAddress((void**)&pwqkv, g_wqkv);
    cudaGetSymbolAddress((void**)&pwow,  g_wow);
    cudaGetSymbolAddress((void**)&pw1w,  g_w1w);
    cudaGetSymbolAddress((void**)&pw2w,  g_w2w);
    cudaGetSymbolAddress((void**)&pwew,  g_wew);
    cudaGetSymbolAddress((void**)&ptok,  g_tok);

    const int SMG = 3 * (16384 + 16384);   // 98304: 3-stage A+B
    const int SMA = 8192 + 32768 + 32768;  // 73728: fused attention
    const int SML = VV * 4;                // 120000: log-softmax staging
    cudaFuncSetAttribute(tgemm_k<EP_QKV>,   cudaFuncAttributeMaxDynamicSharedMemorySize, SMG);
    cudaFuncSetAttribute(tgemm_k<EP_OPROJ>, cudaFuncAttributeMaxDynamicSharedMemorySize, SMG);
    cudaFuncSetAttribute(tgemm_k<EP_FFN1>,  cudaFuncAttributeMaxDynamicSharedMemorySize, SMG);
    cudaFuncSetAttribute(tgemm_k<EP_FFN2>,  cudaFuncAttributeMaxDynamicSharedMemorySize, SMG);
    cudaFuncSetAttribute(tgemm_k<EP_HEAD>,  cudaFuncAttributeMaxDynamicSharedMemorySize, SMG);
    cudaFuncSetAttribute(fattn_k,           cudaFuncAttributeMaxDynamicSharedMemorySize, SMA);
    cudaFuncSetAttribute(logsoftmax_k,      cudaFuncAttributeMaxDynamicSharedMemorySize, SML);

    // ---- weight/bias packing (bf16, [N,K]) ----
    packb_k<<<9, 256>>>(bq, bk, bv, pbqkv);
    packT_k<<<dim3(12, 12), 256>>>(wq, pwqkv,               DD, DD, DD);
    packT_k<<<dim3(12, 12), 256>>>(wk, pwqkv + DD * DD,     DD, DD, DD);
    packT_k<<<dim3(12, 12), 256>>>(wv, pwqkv + 2 * DD * DD, DD, DD, DD);
    packT_k<<<dim3(12, 12), 256>>>(wo, pwow,                DD, DD, DD);
    packT_k<<<dim3(48, 12), 256>>>(w1, pw1w,                DD, FF_, FF_);
    packT_k<<<dim3(12, 48), 256>>>(w2, pw2w,                FF_, DD, DD);
    packT_k<<<dim3(470, 12), 256>>>(we, pwew,               DD, VV, VPAD);

    // ---- embedding ----
    findtok_k<<<BB * SS, 256>>>(onehot, ptok);
    embed_k<<<BB * SS, 256>>>(se_w, se_b, ptok, px, pxb);

    for (int l = 0; l < NLAYERS; l++) {
        // QKV fused: [2048,768] @ [2304,768]^T -> per-head q/k/v (bf16)
        tgemm_k<EP_QKV><<<dim3(18, 16), 256, SMG>>>(
            pxb, pwqkv, DD, DD, DD, pbqkv, nullptr);

        // fused attention -> g_ob (bf16, heads concatenated)
        fattn_k<<<dim3(SS / 64, BB * HH), 128, SMA>>>();

        // o @ wo + bo + x -> y (fp32)
        tgemm_k<EP_OPROJ><<<dim3(6, 16), 256, SMG>>>(
            pob, pwow, DD, DD, DD, bo, nullptr);

        layernorm_k<<<BB * SS, 256>>>(py, plnb);

        // relu(ln @ w1 + b1) -> h1b (bf16)
        tgemm_k<EP_FFN1><<<dim3(24, 16), 256, SMG>>>(
            plnb, pw1w, DD, DD, DD, b1, nullptr);

        // h1 @ w2 + b2 -> x (fp32) + xb (bf16)
        tgemm_k<EP_FFN2><<<dim3(6, 16), 256, SMG>>>(
            ph1b, pw2w, FF_, FF_, FF_, b2, nullptr);
    }

    // gather + vocab head + log_softmax
    gather_k<<<BB * MM, 256>>>(pxb, idx, pgb);
    tgemm_k<EP_HEAD><<<dim3(VPAD / 128, 2), 256, SMG>>>(
        pgb, pwew, DD, DD, DD, be, out);
    logsoftmax_k<<<BB * MM, 256, SML>>>(out);
}

// round 13
// speedup vs baseline: 7.7335x; 1.0622x over previous
#include <cuda_runtime.h>
#include <cuda_bf16.h>
#include <math.h>

// ---------------- problem constants ----------------
#define BB 4
#define SS 512
#define DD 768
#define FF_ 3072
#define VV 30000
#define VPAD 30080
#define HH 12
#define MM 64
#define DH 64
#define NLAYERS 12

// ---------------- static device scratch ----------------
__device__ float g_x  [BB*SS*DD];
__device__ float g_y  [BB*SS*DD];
__device__ float g_bqkv[3*DD];
__device__ __nv_bfloat16 g_xb  [BB*SS*DD];
__device__ __nv_bfloat16 g_lnb [BB*SS*DD];
__device__ __nv_bfloat16 g_ob  [BB*SS*DD];
__device__ __nv_bfloat16 g_qb  [BB*HH*SS*DH];
__device__ __nv_bfloat16 g_kb  [BB*HH*SS*DH];
__device__ __nv_bfloat16 g_vb  [BB*HH*SS*DH];
__device__ __nv_bfloat16 g_h1b [BB*SS*FF_];
__device__ __nv_bfloat16 g_gb  [BB*MM*DD];
__device__ __nv_bfloat16 g_wqkv[3*DD*DD];   // [n=2304][k=768]
__device__ __nv_bfloat16 g_wow [DD*DD];     // [n][k]
__device__ __nv_bfloat16 g_w1w [FF_*DD];    // [3072][768]
__device__ __nv_bfloat16 g_w2w [DD*FF_];    // [768][3072]
__device__ __nv_bfloat16 g_wew [VPAD*DD];   // [30080][768], rows >= 30000 zero
__device__ int g_tok[BB*SS];

// ====================== PTX helpers (arch-portable) ====================
__device__ __forceinline__ unsigned smem_u32(const void* p) {
    unsigned a;
    asm("{ .reg .u64 t; cvta.to.shared.u64 t, %1; cvt.u32.u64 %0, t; }" : "=r"(a) : "l"(p));
    return a;
}
#define SWZ(off) ((unsigned)(off) ^ (((unsigned)(off) >> 3) & 0x70u))

#define CP_ASYNC16(dst, src) \
    asm volatile("cp.async.cg.shared.global [%0], [%1], 16;" :: "r"(dst), "l"(src))
#define CP_COMMIT() asm volatile("cp.async.commit_group;" ::: "memory")
#define CP_WAIT2()  asm volatile("cp.async.wait_group 2;" ::: "memory")
#define CP_WAIT1()  asm volatile("cp.async.wait_group 1;" ::: "memory")
#define CP_WAIT0()  asm volatile("cp.async.wait_group 0;" ::: "memory")

#define LDSM4(r, addr) \
    asm volatile("ldmatrix.sync.aligned.m8n8.x4.shared.b16 {%0,%1,%2,%3}, [%4];" \
        : "=r"((r)[0]), "=r"((r)[1]), "=r"((r)[2]), "=r"((r)[3]) : "r"(addr))

#define LDSM4T(r, addr) \
    asm volatile("ldmatrix.sync.aligned.m8n8.x4.trans.shared.b16 {%0,%1,%2,%3}, [%4];" \
        : "=r"((r)[0]), "=r"((r)[1]), "=r"((r)[2]), "=r"((r)[3]) : "r"(addr))

#define MMA16816(c, a, b0, b1) \
    asm volatile("mma.sync.aligned.m16n8k16.row.col.f32.bf16.bf16.f32 " \
        "{%0,%1,%2,%3}, {%4,%5,%6,%7}, {%8,%9}, {%0,%1,%2,%3};" \
        : "+f"((c)[0]), "+f"((c)[1]), "+f"((c)[2]), "+f"((c)[3]) \
        : "r"((a)[0]), "r"((a)[1]), "r"((a)[2]), "r"((a)[3]), "r"(b0), "r"(b1))

__device__ __forceinline__ unsigned pack_bf16x2(float lo, float hi) {
    __nv_bfloat162 h = __float22bfloat162_rn(make_float2(lo, hi));
    return *(unsigned*)&h;
}

// ---------------- epilogue modes ----------------
#define EP_QKV   0
#define EP_OPROJ 1
#define EP_FFN1  2
#define EP_FFN2  3
#define EP_HEAD  4

// paired store: columns (c, c+1), c even, same row r
template<int EPI>
__device__ __forceinline__ void epi_store2(int r, int c, float v0, float v1,
                                           const float* __restrict__ bias,
                                           float* __restrict__ outp)
{
    if (EPI == EP_QKV) {
        int b = r >> 9, s = r & 511;
        float a0 = v0 + bias[c], a1 = v1 + bias[c + 1];
        int which = c / DD, rr = c - which * DD, h = rr >> 6, d = rr & 63;
        __nv_bfloat16* dst = (which == 0) ? g_qb : (which == 1) ? g_kb : g_vb;
        unsigned pv = pack_bf16x2(a0, a1);
        *(unsigned*)(dst + ((size_t)(b * HH + h) * SS + s) * DH + d) = pv;
    } else if (EPI == EP_OPROJ) {
        size_t off = (size_t)r * DD + c;
        float2 res = *(const float2*)(g_x + off);
        float2 o = make_float2(v0 + bias[c] + res.x, v1 + bias[c + 1] + res.y);
        *(float2*)(g_y + off) = o;
    } else if (EPI == EP_FFN1) {
        unsigned pv = pack_bf16x2(fmaxf(v0 + bias[c], 0.f), fmaxf(v1 + bias[c + 1], 0.f));
        *(unsigned*)(g_h1b + (size_t)r * FF_ + c) = pv;
    } else if (EPI == EP_FFN2) {
        size_t off = (size_t)r * DD + c;
        float a0 = v0 + bias[c], a1 = v1 + bias[c + 1];
        *(float2*)(g_x + off) = make_float2(a0, a1);
        *(unsigned*)(g_xb + off) = pack_bf16x2(a0, a1);
    } else { // EP_HEAD
        if (c < VV)
            *(float2*)(outp + (size_t)r * VV + c) =
                make_float2(v0 + bias[c], v1 + bias[c + 1]);
    }
}

// ======================================================================
// bf16 mma.sync GEMM:  D[MT x 128] = A_tile @ B_tile^T  (fp32 accum)
// A: [M,K] bf16 K-major (lda).  B: [N,K] bf16 K-major (ldb).
// Grid: (N/128, M/MT).  K multiple of 64.  BK=64, 3-stage cp.async,
// SW128-swizzled smem, ldmatrix.x4 fragments, fused per-mode epilogue.
// MT in {64,128}.  8 warps arranged (MT/32) x (8/(MT/32)).
// __launch_bounds__(256,2): 2 CTAs/SM for latency hiding.
// ======================================================================
template<int EPI, int MT>
__global__ void __launch_bounds__(256, 2)
tgemm_k(const __nv_bfloat16* __restrict__ A, const __nv_bfloat16* __restrict__ B,
        int K, int lda, int ldb,
        const float* __restrict__ bias, float* __restrict__ outp)
{
    extern __shared__ char dsm[];
    constexpr int ABUF = MT * 128;
    constexpr int BBUF = 128 * 128;
    constexpr int WMC  = MT / 32;        // warps along M
    constexpr int WNC  = 8 / WMC;        // warps along N
    constexpr int WN   = 128 / WNC;      // n-extent per warp
    constexpr int NTW  = WN / 8;         // 8-wide n-tiles per warp

    const int tid  = threadIdx.x;
    const int lane = tid & 31, wid = tid >> 5;
    const int wm = wid % WMC, wn = wid / WMC;
    const int m0 = blockIdx.y * MT, n0 = blockIdx.x * 128;
    const unsigned sb = smem_u32(dsm);

    A += (size_t)m0 * lda;
    B += (size_t)n0 * ldb;

    const int NC = K >> 6;

    float acc[2][NTW][4];
#pragma unroll
    for (int i = 0; i < 2; i++)
#pragma unroll
        for (int j = 0; j < NTW; j++)
#pragma unroll
            for (int k = 0; k < 4; k++) acc[i][j][k] = 0.f;

    auto load_chunk = [&](int kc, int buf) {
        const __nv_bfloat16* Ap = A + kc * 64;
        unsigned ab = sb + buf * ABUF;
#pragma unroll
        for (int i = 0; i < MT / 32; i++) {
            int ch = tid + i * 256;
            int row = ch >> 3, c = ch & 7;
            CP_ASYNC16(ab + SWZ(row * 128 + c * 16), Ap + (size_t)row * lda + c * 8);
        }
        const __nv_bfloat16* Bp = B + kc * 64;
        unsigned bb = sb + 3 * ABUF + buf * BBUF;
#pragma unroll
        for (int i = 0; i < 4; i++) {
            int ch = tid + i * 256;
            int row = ch >> 3, c = ch & 7;
            CP_ASYNC16(bb + SWZ(row * 128 + c * 16), Bp + (size_t)row * ldb + c * 8);
        }
    };

    load_chunk(0, 0); CP_COMMIT();
    if (NC > 1) load_chunk(1, 1);
    CP_COMMIT();

    const int a_row = (lane & 15);
    const int a_half = (lane >> 4);
    const int b_noff = (lane & 7) + ((lane >> 4) << 3);
    const int b_half = (lane >> 3) & 1;

    for (int kc = 0; kc < NC; kc++) {
        const int buf = kc % 3;
        if (kc + 2 < NC) load_chunk(kc + 2, (kc + 2) % 3);
        CP_COMMIT();
        CP_WAIT2();
        __syncthreads();

        const unsigned ab = sb + buf * ABUF;
        const unsigned bb = sb + 3 * ABUF + buf * BBUF;
#pragma unroll
        for (int ks = 0; ks < 4; ks++) {
            unsigned a[2][4];
#pragma unroll
            for (int mt = 0; mt < 2; mt++) {
                int row = wm * 32 + mt * 16 + a_row;
                LDSM4(a[mt], ab + SWZ(row * 128 + ks * 32 + a_half * 16));
            }
#pragma unroll
            for (int ntp = 0; ntp < NTW / 2; ntp++) {
                unsigned b[4];
                int nrow = wn * WN + ntp * 16 + b_noff;
                LDSM4(b, bb + SWZ(nrow * 128 + ks * 32 + b_half * 16));
#pragma unroll
                for (int mt = 0; mt < 2; mt++) {
                    MMA16816(acc[mt][2 * ntp],     a[mt], b[0], b[1]);
                    MMA16816(acc[mt][2 * ntp + 1], a[mt], b[2], b[3]);
                }
            }
        }
        __syncthreads();
    }

    // ---- epilogue (paired stores: c0,c0+1) ----
    const int g = lane >> 2, t = lane & 3;
#pragma unroll
    for (int mt = 0; mt < 2; mt++) {
#pragma unroll
        for (int nt = 0; nt < NTW; nt++) {
            int r0 = m0 + wm * 32 + mt * 16 + g;
            int c0 = n0 + wn * WN + nt * 8 + t * 2;
            epi_store2<EPI>(r0,     c0, acc[mt][nt][0], acc[mt][nt][1], bias, outp);
            epi_store2<EPI>(r0 + 8, c0, acc[mt][nt][2], acc[mt][nt][3], bias, outp);
        }
    }
}

// ======================================================================
// Fused attention: per CTA one (b,h) and 64 query rows.
// S = scale * Q Kc^T (mma), online softmax in regs, O += P Vc (mma).
// Q,K,V: [z][s][DH] bf16 K-major.  V transpose via ldmatrix.x4.trans.
// Block 128 threads (4 warps x 16 rows). K/V chunks of 128, double buffer.
// ======================================================================
__global__ void __launch_bounds__(128)
fattn_k()
{
    extern __shared__ char dsm[];
    const unsigned sb = smem_u32(dsm);
    const int tid = threadIdx.x, lane = tid & 31, w = tid >> 5;
    const int z = blockIdx.y;
    const int b = z / HH, h = z - b * HH;
    const int q0 = blockIdx.x * 64;

    const __nv_bfloat16* Q  = g_qb + (size_t)z * SS * DH + (size_t)q0 * DH;
    const __nv_bfloat16* Kp = g_kb + (size_t)z * SS * DH;
    const __nv_bfloat16* Vp = g_vb + (size_t)z * SS * DH;

    const unsigned QS = sb;                 // 8 KB
    const unsigned KS = sb + 8192;          // 2 x 16 KB
    const unsigned VS = sb + 8192 + 32768;  // 2 x 16 KB

#pragma unroll
    for (int i = 0; i < 4; i++) {
        int ch = tid + i * 128, row = ch >> 3, c = ch & 7;
        CP_ASYNC16(QS + SWZ(row * 128 + c * 16), Q + (size_t)row * DH + c * 8);
    }
    auto loadKV = [&](int kc, int buf) {
        const __nv_bfloat16* Kc = Kp + (size_t)(kc * 128) * DH;
        unsigned kb = KS + buf * 16384;
#pragma unroll
        for (int i = 0; i < 8; i++) {
            int ch = tid + i * 128, row = ch >> 3, c = ch & 7;
            CP_ASYNC16(kb + SWZ(row * 128 + c * 16), Kc + (size_t)row * DH + c * 8);
        }
        const __nv_bfloat16* Vc = Vp + (size_t)(kc * 128) * DH;
        unsigned vb = VS + buf * 16384;
#pragma unroll
        for (int i = 0; i < 8; i++) {
            int ch = tid + i * 128, row = ch >> 3, c = ch & 7;
            CP_ASYNC16(vb + SWZ(row * 128 + c * 16), Vc + (size_t)row * DH + c * 8);
        }
    };
    loadKV(0, 0); CP_COMMIT();
    loadKV(1, 1); CP_COMMIT();

    float oacc[8][4];
#pragma unroll
    for (int j = 0; j < 8; j++)
#pragma unroll
        for (int k = 0; k < 4; k++) oacc[j][k] = 0.f;
    float m0 = -1e30f, m1 = -1e30f, l0 = 0.f, l1 = 0.f;

    const int a_row = (lane & 15), a_half = (lane >> 4);
    const int b_noff = (lane & 7) + ((lane >> 4) << 3), b_half = (lane >> 3) & 1;
    const int g = lane >> 2, t4 = lane & 3;
    const int v_row = (lane & 7) + ((lane >> 3) & 1) * 8;
    const int v_col = (lane >> 4) * 16;

    for (int kc = 0; kc < 4; kc++) {
        if (kc < 3) CP_WAIT1(); else CP_WAIT0();
        __syncthreads();
        const unsigned kb = KS + (kc & 1) * 16384;
        const unsigned vb = VS + (kc & 1) * 16384;

        float sacc[16][4];
#pragma unroll
        for (int j = 0; j < 16; j++)
#pragma unroll
            for (int k = 0; k < 4; k++) sacc[j][k] = 0.f;
#pragma unroll
        for (int ks = 0; ks < 4; ks++) {
            unsigned aq[4];
            LDSM4(aq, QS + SWZ((w * 16 + a_row) * 128 + ks * 32 + a_half * 16));
#pragma unroll
            for (int ntp = 0; ntp < 8; ntp++) {
                unsigned bk[4];
                LDSM4(bk, kb + SWZ((ntp * 16 + b_noff) * 128 + ks * 32 + b_half * 16));
                MMA16816(sacc[2 * ntp],     aq, bk[0], bk[1]);
                MMA16816(sacc[2 * ntp + 1], aq, bk[2], bk[3]);
            }
        }
        float mx0 = -1e30f, mx1 = -1e30f;
#pragma unroll
        for (int j = 0; j < 16; j++) {
            sacc[j][0] *= 0.125f; sacc[j][1] *= 0.125f;
            sacc[j][2] *= 0.125f; sacc[j][3] *= 0.125f;
            mx0 = fmaxf(mx0, fmaxf(sacc[j][0], sacc[j][1]));
            mx1 = fmaxf(mx1, fmaxf(sacc[j][2], sacc[j][3]));
        }
        mx0 = fmaxf(mx0, __shfl_xor_sync(0xffffffffu, mx0, 1));
        mx0 = fmaxf(mx0, __shfl_xor_sync(0xffffffffu, mx0, 2));
        mx1 = fmaxf(mx1, __shfl_xor_sync(0xffffffffu, mx1, 1));
        mx1 = fmaxf(mx1, __shfl_xor_sync(0xffffffffu, mx1, 2));
        float nm0 = fmaxf(m0, mx0), nm1 = fmaxf(m1, mx1);
        float al0 = expf(m0 - nm0), al1 = expf(m1 - nm1);
        m0 = nm0; m1 = nm1;
        float rs0 = 0.f, rs1 = 0.f;
#pragma unroll
        for (int j = 0; j < 16; j++) {
            sacc[j][0] = expf(sacc[j][0] - m0); sacc[j][1] = expf(sacc[j][1] - m0);
            sacc[j][2] = expf(sacc[j][2] - m1); sacc[j][3] = expf(sacc[j][3] - m1);
            rs0 += sacc[j][0] + sacc[j][1];
            rs1 += sacc[j][2] + sacc[j][3];
        }
        rs0 += __shfl_xor_sync(0xffffffffu, rs0, 1);
        rs0 += __shfl_xor_sync(0xffffffffu, rs0, 2);
        rs1 += __shfl_xor_sync(0xffffffffu, rs1, 1);
        rs1 += __shfl_xor_sync(0xffffffffu, rs1, 2);
        l0 = l0 * al0 + rs0;
        l1 = l1 * al1 + rs1;
#pragma unroll
        for (int j = 0; j < 8; j++) {
            oacc[j][0] *= al0; oacc[j][1] *= al0;
            oacc[j][2] *= al1; oacc[j][3] *= al1;
        }
#pragma unroll
        for (int ksl = 0; ksl < 8; ksl++) {
            unsigned pa[4];
            pa[0] = pack_bf16x2(sacc[2 * ksl][0],     sacc[2 * ksl][1]);
            pa[1] = pack_bf16x2(sacc[2 * ksl][2],     sacc[2 * ksl][3]);
            pa[2] = pack_bf16x2(sacc[2 * ksl + 1][0], sacc[2 * ksl + 1][1]);
            pa[3] = pack_bf16x2(sacc[2 * ksl + 1][2], sacc[2 * ksl + 1][3]);
#pragma unroll
            for (int ntp = 0; ntp < 4; ntp++) {
                unsigned bv[4];
                LDSM4T(bv, vb + SWZ((ksl * 16 + v_row) * 128 + ntp * 32 + v_col));
                MMA16816(oacc[2 * ntp],     pa, bv[0], bv[1]);
                MMA16816(oacc[2 * ntp + 1], pa, bv[2], bv[3]);
            }
        }
        __syncthreads();
        if (kc + 2 < 4) { loadKV(kc + 2, kc & 1); CP_COMMIT(); }
    }

    float inv0 = 1.f / l0, inv1 = 1.f / l1;
    int row0 = q0 + w * 16 + g;
    __nv_bfloat16* Ob = g_ob + (size_t)(b * SS) * DD + h * DH;
#pragma unroll
    for (int j = 0; j < 8; j++) {
        int col = j * 8 + t4 * 2;
        *(__nv_bfloat162*)(Ob + (size_t)row0 * DD + col) =
            __float22bfloat162_rn(make_float2(oacc[j][0] * inv0, oacc[j][1] * inv0));
        *(__nv_bfloat162*)(Ob + (size_t)(row0 + 8) * DD + col) =
            __float22bfloat162_rn(make_float2(oacc[j][2] * inv1, oacc[j][3] * inv1));
    }
}

// ======================================================================
// weight transpose+pack: src fp32 [K,N] -> dst bf16 [Npad,K] (64x64 tiles)
// ======================================================================
__global__ void __launch_bounds__(256)
packT_k(const float* __restrict__ src, __nv_bfloat16* __restrict__ dst,
        int K, int N, int Npad)
{
    __shared__ float ts[64][65];
    int n0 = blockIdx.x * 64, k0 = blockIdx.y * 64;
    int t = threadIdx.x;
    int kr = t >> 2, cq = t & 3;
#pragma unroll
    for (int i = 0; i < 4; i++) {
        int nc = (cq + i * 4) * 4;
        int n = n0 + nc;
        const float* sp = src + (size_t)(k0 + kr) * N;
        float4 v;
        if (n + 3 < N) v = *(const float4*)(sp + n);
        else {
            v.x = (n + 0 < N) ? sp[n + 0] : 0.f;
            v.y = (n + 1 < N) ? sp[n + 1] : 0.f;
            v.z = (n + 2 < N) ? sp[n + 2] : 0.f;
            v.w = (n + 3 < N) ? sp[n + 3] : 0.f;
        }
        ts[kr][nc] = v.x; ts[kr][nc + 1] = v.y; ts[kr][nc + 2] = v.z; ts[kr][nc + 3] = v.w;
    }
    __syncthreads();
    int nr = t >> 2, ks = (t & 3) * 16;
    if (n0 + nr < Npad) {
        unsigned ov[8];
#pragma unroll
        for (int e = 0; e < 8; e++)
            ov[e] = pack_bf16x2(ts[ks + 2 * e][nr], ts[ks + 2 * e + 1][nr]);
        __nv_bfloat16* dp = dst + (size_t)(n0 + nr) * K + k0 + ks;
        *(uint4*)dp       = make_uint4(ov[0], ov[1], ov[2], ov[3]);
        *(uint4*)(dp + 8) = make_uint4(ov[4], ov[5], ov[6], ov[7]);
    }
}

__global__ void packb_k(const float* __restrict__ bq, const float* __restrict__ bk,
                        const float* __restrict__ bv, float* __restrict__ dst)
{
    int i = blockIdx.x * 256 + threadIdx.x;
    if (i < DD) dst[i] = bq[i];
    else if (i < 2 * DD) dst[i] = bk[i - DD];
    else if (i < 3 * DD) dst[i] = bv[i - 2 * DD];
}

// ======================================================================
// one-hot -> token id (float4 scan)
// ======================================================================
__global__ void findtok_k(const float* __restrict__ oh, int* __restrict__ tok)
{
    size_t row = blockIdx.x;
    const float4* r = (const float4*)(oh + row * (size_t)VV);
    for (int j = threadIdx.x; j < VV / 4; j += blockDim.x) {
        float4 v = r[j];
        if (v.x > 0.5f) tok[row] = 4 * j;
        else if (v.y > 0.5f) tok[row] = 4 * j + 1;
        else if (v.z > 0.5f) tok[row] = 4 * j + 2;
        else if (v.w > 0.5f) tok[row] = 4 * j + 3;
    }
}

// ======================================================================
// x = se_w[tok] + se_b + positional encoding ; also bf16 mirror
// ======================================================================
__global__ void embed_k(const float* __restrict__ se_w, const float* __restrict__ se_b,
                        const int* __restrict__ tok, float* __restrict__ x,
                        __nv_bfloat16* __restrict__ xb)
{
    int row = blockIdx.x;
    int s   = row & (SS - 1);
    int tk  = tok[row];
    const float* wrow = se_w + (size_t)tk * DD;
    float* xr = x + (size_t)row * DD;
    __nv_bfloat16* xbr = xb + (size_t)row * DD;
    for (int d = threadIdx.x; d < DD; d += blockDim.x) {
        float pe = 0.f;
        if (s != 0) {
            float denom = powf(10000.0f, (2.0f * (float)d) / (float)DD);
            float raw   = (float)s / denom;
            pe = (d & 1) ? cosf(raw) : sinf(raw);
        }
        float v = wrow[d] + se_b[d] + pe;
        xr[d] = v;
        xbr[d] = __float2bfloat16(v);
    }
}

// ======================================================================
// layernorm over D=768 (fp32 in -> bf16 out)
// ======================================================================
__global__ void layernorm_k(const float* __restrict__ y, __nv_bfloat16* __restrict__ x)
{
    __shared__ float rs[8], rq[8];
    size_t row = blockIdx.x;
    const float* yp = y + row * DD;
    __nv_bfloat16* xp = x + row * DD;
    int t = threadIdx.x;
    float a0 = yp[t], a1 = yp[t + 256], a2 = yp[t + 512];
    float s = a0 + a1 + a2;
    float q = a0 * a0 + a1 * a1 + a2 * a2;
#pragma unroll
    for (int o = 16; o; o >>= 1) {
        s += __shfl_xor_sync(0xffffffffu, s, o);
        q += __shfl_xor_sync(0xffffffffu, q, o);
    }
    if ((t & 31) == 0) { rs[t >> 5] = s; rq[t >> 5] = q; }
    __syncthreads();
    s = rs[0] + rs[1] + rs[2] + rs[3] + rs[4] + rs[5] + rs[6] + rs[7];
    q = rq[0] + rq[1] + rq[2] + rq[3] + rq[4] + rq[5] + rq[6] + rq[7];
    float mean = s * (1.0f / (float)DD);
    float var  = q * (1.0f / (float)DD) - mean * mean;
    float r = rsqrtf(var + 1e-5f);
    xp[t]       = __float2bfloat16((a0 - mean) * r);
    xp[t + 256] = __float2bfloat16((a1 - mean) * r);
    xp[t + 512] = __float2bfloat16((a2 - mean) * r);
}

// ======================================================================
// gather masked rows (bf16 -> bf16)
// ======================================================================
__global__ void gather_k(const __nv_bfloat16* __restrict__ x, const int* __restrict__ idx,
                         __nv_bfloat16* __restrict__ g)
{
    int r = blockIdx.x;
    int b = r >> 6;
    int s = idx[r];
    const __nv_bfloat16* src = x + ((size_t)(b * SS + s)) * DD;
    __nv_bfloat16* dst = g + (size_t)r * DD;
    for (int d = threadIdx.x; d < DD; d += blockDim.x) dst[d] = src[d];
}

// ======================================================================
// in-place log_softmax over V=30000 — single gmem read via smem staging
// ======================================================================
__global__ void logsoftmax_k(float* __restrict__ out)
{
    extern __shared__ float buf[];       // 30000 floats = 117.2 KB
    __shared__ float red[8];
    size_t row = blockIdx.x;
    float* p = out + row * (size_t)VV;
    int t = threadIdx.x;

    float m = -1e30f;
    for (int j = t; j < VV / 4; j += 256) {
        float4 v = *(const float4*)(p + 4 * j);
        *(float4*)(buf + 4 * j) = v;
        m = fmaxf(fmaxf(m, fmaxf(v.x, v.y)), fmaxf(v.z, v.w));
    }
#pragma unroll
    for (int o = 16; o; o >>= 1) m = fmaxf(m, __shfl_xor_sync(0xffffffffu, m, o));
    if ((t & 31) == 0) red[t >> 5] = m;
    __syncthreads();
    m = fmaxf(fmaxf(fmaxf(red[0], red[1]), fmaxf(red[2], red[3])),
              fmaxf(fmaxf(red[4], red[5]), fmaxf(red[6], red[7])));

    float s = 0.f;
    for (int j = t; j < VV / 4; j += 256) {
        float4 v = *(const float4*)(buf + 4 * j);
        s += expf(v.x - m) + expf(v.y - m) + expf(v.z - m) + expf(v.w - m);
    }
#pragma unroll
    for (int o = 16; o; o >>= 1) s += __shfl_xor_sync(0xffffffffu, s, o);
    __syncthreads();
    if ((t & 31) == 0) red[t >> 5] = s;
    __syncthreads();
    s = red[0] + red[1] + red[2] + red[3] + red[4] + red[5] + red[6] + red[7];

    float lse = m + logf(s);
    for (int j = t; j < VV / 4; j += 256) {
        float4 v = *(const float4*)(buf + 4 * j);
        *(float4*)(p + 4 * j) = make_float4(v.x - lse, v.y - lse, v.z - lse, v.w - lse);
    }
}

// ======================================================================
// launcher
// ======================================================================
extern "C" void kernel_launch(void* const* d_in, const int* in_sizes, int n_in,
                              void* d_out, int out_size)
{
    (void)in_sizes; (void)n_in; (void)out_size;
    const float* onehot = (const float*)d_in[0];
    const float* se_w = (const float*)d_in[1];
    const float* se_b = (const float*)d_in[2];
    const float* wq = (const float*)d_in[3];  const float* bq = (const float*)d_in[4];
    const float* wk = (const float*)d_in[5];  const float* bk = (const float*)d_in[6];
    const float* wv = (const float*)d_in[7];  const float* bv = (const float*)d_in[8];
    const float* wo = (const float*)d_in[9];  const float* bo = (const float*)d_in[10];
    const float* w1 = (const float*)d_in[11]; const float* b1 = (const float*)d_in[12];
    const float* w2 = (const float*)d_in[13]; const float* b2 = (const float*)d_in[14];
    const float* we = (const float*)d_in[15]; const float* be = (const float*)d_in[16];
    const int*   idx = (const int*)d_in[17];
    float* out = (float*)d_out;

    float *px, *py, *pbqkv;
    __nv_bfloat16 *pxb, *plnb, *pob, *ph1b, *pgb;
    __nv_bfloat16 *pwqkv, *pwow, *pw1w, *pw2w, *pwew;
    int* ptok;
    cudaGetSymbolAddress((void**)&px,    g_x);
    cudaGetSymbolAddress((void**)&py,    g_y);
    cudaGetSymbolAddress((void**)&pbqkv, g_bqkv);
    cudaGetSymbolAddress((void**)&pxb,   g_xb);
    cudaGetSymbolAddress((void**)&plnb,  g_lnb);
    cudaGetSymbolAddress((void**)&pob,   g_ob);
    cudaGetSymbolAddress((void**)&ph1b,  g_h1b);
    cudaGetSymbolAddress((void**)&pgb,   g_gb);
    cudaGetSymbolAddress((void**)&pwqkv, g_wqkv);
    cudaGetSymbolAddress((void**)&pwow,  g_wow);
    cudaGetSymbolAddress((void**)&pw1w,  g_w1w);
    cudaGetSymbolAddress((void**)&pw2w,  g_w2w);
    cudaGetSymbolAddress((void**)&pwew,  g_wew);
    cudaGetSymbolAddress((void**)&ptok,  g_tok);

    const int SMG128 = 3 * (16384 + 16384);   // 98304
    const int SMG64  = 3 * (8192 + 16384);    // 73728
    const int SMA = 8192 + 32768 + 32768;     // 73728
    const int SML = VV * 4;                   // 120000
    cudaFuncSetAttribute(tgemm_k<EP_QKV,  128>, cudaFuncAttributeMaxDynamicSharedMemorySize, SMG128);
    cudaFuncSetAttribute(tgemm_k<EP_OPROJ, 64>, cudaFuncAttributeMaxDynamicSharedMemorySize, SMG64);
    cudaFuncSetAttribute(tgemm_k<EP_FFN1, 128>, cudaFuncAttributeMaxDynamicSharedMemorySize, SMG128);
    cudaFuncSetAttribute(tgemm_k<EP_FFN2,  64>, cudaFuncAttributeMaxDynamicSharedMemorySize, SMG64);
    cudaFuncSetAttribute(tgemm_k<EP_HEAD, 128>, cudaFuncAttributeMaxDynamicSharedMemorySize, SMG128);
    cudaFuncSetAttribute(fattn_k,               cudaFuncAttributeMaxDynamicSharedMemorySize, SMA);
    cudaFuncSetAttribute(logsoftmax_k,          cudaFuncAttributeMaxDynamicSharedMemorySize, SML);

    // ---- weight/bias packing (bf16, [N,K]) ----
    packb_k<<<9, 256>>>(bq, bk, bv, pbqkv);
    packT_k<<<dim3(12, 12), 256>>>(wq, pwqkv,               DD, DD, DD);
    packT_k<<<dim3(12, 12), 256>>>(wk, pwqkv + DD * DD,     DD, DD, DD);
    packT_k<<<dim3(12, 12), 256>>>(wv, pwqkv + 2 * DD * DD, DD, DD, DD);
    packT_k<<<dim3(12, 12), 256>>>(wo, pwow,                DD, DD, DD);
    packT_k<<<dim3(48, 12), 256>>>(w1, pw1w,                DD, FF_, FF_);
    packT_k<<<dim3(12, 48), 256>>>(w2, pw2w,                FF_, DD, DD);
    packT_k<<<dim3(470, 12), 256>>>(we, pwew,               DD, VV, VPAD);

    // ---- embedding ----
    findtok_k<<<BB * SS, 256>>>(onehot, ptok);
    embed_k<<<BB * SS, 256>>>(se_w, se_b, ptok, px, pxb);

    for (int l = 0; l < NLAYERS; l++) {
        // QKV fused: [2048,768] @ [2304,768]^T -> per-head q/k/v (bf16)
        tgemm_k<EP_QKV, 128><<<dim3(18, 16), 256, SMG128>>>(
            pxb, pwqkv, DD, DD, DD, pbqkv, nullptr);

        // fused attention -> g_ob (bf16, heads concatenated)
        fattn_k<<<dim3(SS / 64, BB * HH), 128, SMA>>>();

        // o @ wo + bo + x -> y (fp32)   [64x128 tiles -> 192 CTAs]
        tgemm_k<EP_OPROJ, 64><<<dim3(6, 32), 256, SMG64>>>(
            pob, pwow, DD, DD, DD, bo, nullptr);

        layernorm_k<<<BB * SS, 256>>>(py, plnb);

        // relu(ln @ w1 + b1) -> h1b (bf16)
        tgemm_k<EP_FFN1, 128><<<dim3(24, 16), 256, SMG128>>>(
            plnb, pw1w, DD, DD, DD, b1, nullptr);

        // h1 @ w2 + b2 -> x (fp32) + xb (bf16)   [64x128 tiles -> 192 CTAs]
        tgemm_k<EP_FFN2, 64><<<dim3(6, 32), 256, SMG64>>>(
            ph1b, pw2w, FF_, FF_, FF_, b2, nullptr);
    }

    // gather + vocab head + log_softmax
    gather_k<<<BB * MM, 256>>>(pxb, idx, pgb);
    tgemm_k<EP_HEAD, 128><<<dim3(VPAD / 128, 2), 256, SMG128>>>(
        pgb, pwew, DD, DD, DD, be, out);
    logsoftmax_k<<<BB * MM, 256, SML>>>(out);
}